// round 2
// baseline (speedup 1.0000x reference)
#include <cuda_runtime.h>

#define NN 20000
#define NE 320000
#define NT (NE + NN)

// ---------------- scratch (device globals; no allocations allowed) ----------
__device__ float g_xl[(size_t)NN * 1024];
__device__ float g_skip[(size_t)NN * 1024];
__device__ float g_agg[(size_t)NN * 1024];
__device__ float g_h[(size_t)NN * 1024];
__device__ float g_asrc[NN * 6];
__device__ float g_adst[NN * 6];
__device__ int   g_deg[NN];
__device__ int   g_row[NN + 1];
__device__ int   g_cursor[NN];
__device__ int   g_esrc[NT];
__device__ int   g_edst[NT];
__device__ int   g_csr_src[NT];
__device__ int   g_is64;

// ---------------- edge dtype detection --------------------------------------
// If edge_index is int64, values < 20000 => every odd 32-bit word is zero.
// For int32 data, 1024 consecutive values all being zero is impossible
// (random in [0,20000)). Deterministic, graph-capturable.
__global__ void detect_dtype_kernel(const int* __restrict__ w) {
    if (threadIdx.x == 0) {
        int nz = 0;
        for (int i = 1; i < 2048; i += 2) nz += (w[i] != 0);
        g_is64 = (nz == 0) ? 1 : 0;
    }
}

// ---------------- graph construction ----------------------------------------
__global__ void zero_deg_kernel() {
    int i = blockIdx.x * blockDim.x + threadIdx.x;
    if (i < NN) g_deg[i] = 0;
}

__global__ void build_edges_kernel(const void* __restrict__ ei) {
    int t = blockIdx.x * blockDim.x + threadIdx.x;
    if (t >= NT) return;
    int s, d;
    if (t < NE) {
        if (g_is64) {
            const long long* p = (const long long*)ei;
            s = (int)p[t];
            d = (int)p[NE + t];
        } else {
            const int* p = (const int*)ei;
            s = p[t];
            d = p[NE + t];
        }
        // defensive clamp: a wrong dtype guess shows as rel_err, not a crash
        s = min(max(s, 0), NN - 1);
        d = min(max(d, 0), NN - 1);
    } else {
        s = d = t - NE;  // self loop
    }
    g_esrc[t] = s;
    g_edst[t] = d;
    atomicAdd(&g_deg[d], 1);
}

// single-block chunked inclusive scan -> row offsets + cursor init
__global__ void scan_kernel() {
    __shared__ int sh[1024];
    __shared__ int carry;
    int tid = threadIdx.x;
    if (tid == 0) { carry = 0; g_row[0] = 0; }
    __syncthreads();
    for (int base = 0; base < NN; base += 1024) {
        int i = base + tid;
        int v = (i < NN) ? g_deg[i] : 0;
        sh[tid] = v;
        __syncthreads();
        for (int off = 1; off < 1024; off <<= 1) {
            int t = (tid >= off) ? sh[tid - off] : 0;
            __syncthreads();
            sh[tid] += t;
            __syncthreads();
        }
        if (i < NN) {
            int incl = sh[tid];
            g_row[i + 1]  = carry + incl;
            g_cursor[i]   = carry + incl - v;
        }
        __syncthreads();
        if (tid == 0) carry += sh[1023];
        __syncthreads();
    }
}

__global__ void scatter_kernel() {
    int t = blockIdx.x * blockDim.x + threadIdx.x;
    if (t >= NT) return;
    int d = g_edst[t];
    int pos = atomicAdd(&g_cursor[d], 1);
    g_csr_src[pos] = g_esrc[t];
}

// ---------------- SGEMM: C[M,Nn] = A[M,K] @ B[K,Nn] -------------------------
#define BM 64
#define BN 64
#define BK 16
__global__ __launch_bounds__(256) void sgemm_kernel(
    const float* __restrict__ A, const float* __restrict__ B,
    float* __restrict__ C, int M, int K, int Nn) {
    __shared__ float As[BK][BM];
    __shared__ float Bs[BK][BN];
    int tid = threadIdx.x;
    int tx = tid & 15, ty = tid >> 4;
    int tileM = blockIdx.y * BM, tileN = blockIdx.x * BN;
    float acc[4][4] = {};
    for (int k0 = 0; k0 < K; k0 += BK) {
#pragma unroll
        for (int i = 0; i < 4; i++) {
            int idx = tid + i * 256;
            int r = idx >> 4, c = idx & 15;
            int gm = tileM + r, gk = k0 + c;
            As[c][r] = (gm < M && gk < K) ? A[(size_t)gm * K + gk] : 0.f;
        }
#pragma unroll
        for (int i = 0; i < 4; i++) {
            int idx = tid + i * 256;
            int r = idx & 63, c = idx >> 6;
            int gk = k0 + c, gn = tileN + r;
            Bs[c][r] = (gk < K && gn < Nn) ? B[(size_t)gk * Nn + gn] : 0.f;
        }
        __syncthreads();
#pragma unroll
        for (int k = 0; k < BK; k++) {
            float ra[4], rb[4];
#pragma unroll
            for (int i = 0; i < 4; i++) ra[i] = As[k][ty * 4 + i];
#pragma unroll
            for (int j = 0; j < 4; j++) rb[j] = Bs[k][tx * 4 + j];
#pragma unroll
            for (int i = 0; i < 4; i++)
#pragma unroll
                for (int j = 0; j < 4; j++) acc[i][j] += ra[i] * rb[j];
        }
        __syncthreads();
    }
#pragma unroll
    for (int i = 0; i < 4; i++) {
        int gm = tileM + ty * 4 + i;
        if (gm >= M) continue;
#pragma unroll
        for (int j = 0; j < 4; j++) {
            int gn = tileN + tx * 4 + j;
            if (gn < Nn) C[(size_t)gm * Nn + gn] = acc[i][j];
        }
    }
}

// ---------------- per-node attention logits ---------------------------------
__global__ void compute_alpha_kernel(const float* __restrict__ xl,
                                     const float* __restrict__ a_src,
                                     const float* __restrict__ a_dst,
                                     int H, int C) {
    int n = blockIdx.x;
    int h = threadIdx.x >> 5;
    int lane = threadIdx.x & 31;
    const float* xr = xl + ((size_t)n * H + h) * C;
    float ss = 0.f, sd = 0.f;
    for (int c = lane; c < C; c += 32) {
        float v = xr[c];
        ss += v * a_src[h * C + c];
        sd += v * a_dst[h * C + c];
    }
#pragma unroll
    for (int off = 16; off > 0; off >>= 1) {
        ss += __shfl_down_sync(0xffffffffu, ss, off);
        sd += __shfl_down_sync(0xffffffffu, sd, off);
    }
    if (lane == 0) {
        g_asrc[n * H + h] = ss;
        g_adst[n * H + h] = sd;
    }
}

// ---------------- softmax-aggregate per (dst, head) --------------------------
// out[d,h,:] = sum_j exp(e_j - m) * xl[src_j,h,:] / (sum_j exp(e_j - m) + eps)
// e_j = leakyrelu(asrc[src_j,h] + adst[d,h]); leaky-relu is monotonic so
// max commutes through it.
__global__ void gat_aggregate_kernel(const float* __restrict__ xl,
                                     float* __restrict__ out, int H, int C) {
    int d = blockIdx.x, h = blockIdx.y;
    int tid = threadIdx.x;
    int r0 = g_row[d], r1 = g_row[d + 1];
    float adv = g_adst[d * H + h];

    __shared__ float smax[256];
    float mx = -1e30f;
    for (int j = r0 + tid; j < r1; j += blockDim.x)
        mx = fmaxf(mx, g_asrc[g_csr_src[j] * H + h]);
    smax[tid] = mx;
    __syncthreads();
    for (int s = blockDim.x >> 1; s > 0; s >>= 1) {
        if (tid < s) smax[tid] = fmaxf(smax[tid], smax[tid + s]);
        __syncthreads();
    }
    float m = smax[0] + adv;
    m = (m > 0.f) ? m : 0.2f * m;  // leaky relu

    float acc = 0.f, denom = 0.f;
    for (int j = r0; j < r1; j++) {
        int s = g_csr_src[j];
        float e = g_asrc[s * H + h] + adv;
        e = (e > 0.f) ? e : 0.2f * e;
        float w = __expf(e - m);
        denom += w;
        if (tid < C) acc += w * xl[((size_t)s * H + h) * C + tid];
    }
    if (tid < C)
        out[((size_t)d * H + h) * C + tid] = acc / (denom + 1e-16f);
}

// ---------------- fused add-skip + layernorm + elu ---------------------------
__global__ __launch_bounds__(256) void ln_elu_kernel(
    const float* __restrict__ agg, const float* __restrict__ b,
    const float* __restrict__ skip, const float* __restrict__ skipb,
    const float* __restrict__ g, const float* __restrict__ beta,
    float* __restrict__ out) {
    int row = blockIdx.x;
    int tid = threadIdx.x;
    const size_t base = (size_t)row * 1024;
    float pre[4];
    float sum = 0.f;
#pragma unroll
    for (int k = 0; k < 4; k++) {
        int i = k * 256 + tid;
        pre[k] = agg[base + i] + b[i] + skip[base + i] + skipb[i];
        sum += pre[k];
    }
    __shared__ float red[256];
    red[tid] = sum;
    __syncthreads();
    for (int s = 128; s > 0; s >>= 1) {
        if (tid < s) red[tid] += red[tid + s];
        __syncthreads();
    }
    float mu = red[0] * (1.f / 1024.f);
    __syncthreads();
    float sq = 0.f;
#pragma unroll
    for (int k = 0; k < 4; k++) {
        float dlt = pre[k] - mu;
        sq += dlt * dlt;
    }
    red[tid] = sq;
    __syncthreads();
    for (int s = 128; s > 0; s >>= 1) {
        if (tid < s) red[tid] += red[tid + s];
        __syncthreads();
    }
    float rstd = rsqrtf(red[0] * (1.f / 1024.f) + 1e-5f);
#pragma unroll
    for (int k = 0; k < 4; k++) {
        int i = k * 256 + tid;
        float v = (pre[k] - mu) * rstd * g[i] + beta[i];
        out[base + i] = (v > 0.f) ? v : expm1f(v);  // elu
    }
}

// ---------------- final head-mean + bias -------------------------------------
__global__ void head_mean_kernel(const float* __restrict__ agg,
                                 const float* __restrict__ b3,
                                 float* __restrict__ out) {
    int idx = blockIdx.x * blockDim.x + threadIdx.x;
    if (idx >= NN * 121) return;
    int n = idx / 121, c = idx % 121;
    float s = 0.f;
#pragma unroll
    for (int h = 0; h < 6; h++) s += agg[((size_t)n * 6 + h) * 121 + c];
    out[idx] = s * (1.f / 6.f) + b3[c];
}

// ---------------- host orchestration -----------------------------------------
static void run_sgemm(const float* A, const float* B, float* C, int M, int K, int Nn) {
    dim3 grid((Nn + BN - 1) / BN, (M + BM - 1) / BM);
    sgemm_kernel<<<grid, 256>>>(A, B, C, M, K, Nn);
}

extern "C" void kernel_launch(void* const* d_in, const int* in_sizes, int n_in,
                              void* d_out, int out_size) {
    const float* x      = (const float*)d_in[0];
    const void*  ei     = d_in[1];
    const float* W1     = (const float*)d_in[2];
    const float* a_src1 = (const float*)d_in[3];
    const float* a_dst1 = (const float*)d_in[4];
    const float* b1     = (const float*)d_in[5];
    const float* W2     = (const float*)d_in[6];
    const float* a_src2 = (const float*)d_in[7];
    const float* a_dst2 = (const float*)d_in[8];
    const float* b2     = (const float*)d_in[9];
    const float* W3     = (const float*)d_in[10];
    const float* a_src3 = (const float*)d_in[11];
    const float* a_dst3 = (const float*)d_in[12];
    const float* b3     = (const float*)d_in[13];
    const float* skipW1 = (const float*)d_in[14];
    const float* skipb1 = (const float*)d_in[15];
    const float* skipW2 = (const float*)d_in[16];
    const float* skipb2 = (const float*)d_in[17];
    const float* g1     = (const float*)d_in[18];
    const float* beta1  = (const float*)d_in[19];
    const float* g2     = (const float*)d_in[20];
    const float* beta2  = (const float*)d_in[21];
    float* out = (float*)d_out;

    float *p_xl, *p_skip, *p_agg, *p_h;
    cudaGetSymbolAddress((void**)&p_xl, g_xl);
    cudaGetSymbolAddress((void**)&p_skip, g_skip);
    cudaGetSymbolAddress((void**)&p_agg, g_agg);
    cudaGetSymbolAddress((void**)&p_h, g_h);

    // ---- CSR build (edges shared by all 3 layers) ----
    detect_dtype_kernel<<<1, 32>>>((const int*)ei);
    zero_deg_kernel<<<(NN + 255) / 256, 256>>>();
    build_edges_kernel<<<(NT + 255) / 256, 256>>>(ei);
    scan_kernel<<<1, 1024>>>();
    scatter_kernel<<<(NT + 255) / 256, 256>>>();

    // ---- Layer 1: GATConv(50 -> 256, H=4, concat) ----
    run_sgemm(x, W1, p_xl, NN, 50, 1024);
    run_sgemm(x, skipW1, p_skip, NN, 50, 1024);
    compute_alpha_kernel<<<NN, 4 * 32>>>(p_xl, a_src1, a_dst1, 4, 256);
    gat_aggregate_kernel<<<dim3(NN, 4), 256>>>(p_xl, p_agg, 4, 256);
    ln_elu_kernel<<<NN, 256>>>(p_agg, b1, p_skip, skipb1, g1, beta1, p_h);

    // ---- Layer 2: GATConv(1024 -> 256, H=4, concat) ----
    run_sgemm(p_h, W2, p_xl, NN, 1024, 1024);
    run_sgemm(p_h, skipW2, p_skip, NN, 1024, 1024);
    compute_alpha_kernel<<<NN, 4 * 32>>>(p_xl, a_src2, a_dst2, 4, 256);
    gat_aggregate_kernel<<<dim3(NN, 4), 256>>>(p_xl, p_agg, 4, 256);
    ln_elu_kernel<<<NN, 256>>>(p_agg, b2, p_skip, skipb2, g2, beta2, p_h);

    // ---- Layer 3: GATConv(1024 -> 121, H=6, mean) ----
    run_sgemm(p_h, W3, p_xl, NN, 1024, 726);
    compute_alpha_kernel<<<NN, 6 * 32>>>(p_xl, a_src3, a_dst3, 6, 121);
    gat_aggregate_kernel<<<dim3(NN, 6), 128>>>(p_xl, p_agg, 6, 121);
    head_mean_kernel<<<(NN * 121 + 255) / 256, 256>>>(p_agg, b3, out);
}

// round 3
// speedup vs baseline: 1.3580x; 1.3580x over previous
#include <cuda_runtime.h>

#define NN 20000
#define NE 320000
#define NT (NE + NN)

// ---------------- scratch (device globals; no allocations allowed) ----------
__device__ float g_xl[(size_t)NN * 1024];
__device__ float g_skip[(size_t)NN * 1024];
__device__ float g_agg[(size_t)NN * 1024];
__device__ float g_h[(size_t)NN * 1024];
__device__ float g_asrc[NN * 6];
__device__ float g_adst[NN * 6];
__device__ int   g_deg[NN];
__device__ int   g_row[NN + 1];
__device__ int   g_cursor[NN];
__device__ int   g_esrc[NT];
__device__ int   g_edst[NT];
__device__ int   g_csr_src[NT];
__device__ int   g_is64;

// ---------------- edge dtype detection --------------------------------------
__global__ void detect_dtype_kernel(const int* __restrict__ w) {
    if (threadIdx.x == 0) {
        int nz = 0;
        for (int i = 1; i < 2048; i += 2) nz += (w[i] != 0);
        g_is64 = (nz == 0) ? 1 : 0;
    }
}

// ---------------- graph construction ----------------------------------------
__global__ void zero_deg_kernel() {
    int i = blockIdx.x * blockDim.x + threadIdx.x;
    if (i < NN) g_deg[i] = 0;
}

__global__ void build_edges_kernel(const void* __restrict__ ei) {
    int t = blockIdx.x * blockDim.x + threadIdx.x;
    if (t >= NT) return;
    int s, d;
    if (t < NE) {
        if (g_is64) {
            const long long* p = (const long long*)ei;
            s = (int)p[t];
            d = (int)p[NE + t];
        } else {
            const int* p = (const int*)ei;
            s = p[t];
            d = p[NE + t];
        }
        s = min(max(s, 0), NN - 1);
        d = min(max(d, 0), NN - 1);
    } else {
        s = d = t - NE;  // self loop
    }
    g_esrc[t] = s;
    g_edst[t] = d;
    atomicAdd(&g_deg[d], 1);
}

__global__ void scan_kernel() {
    __shared__ int sh[1024];
    __shared__ int carry;
    int tid = threadIdx.x;
    if (tid == 0) { carry = 0; g_row[0] = 0; }
    __syncthreads();
    for (int base = 0; base < NN; base += 1024) {
        int i = base + tid;
        int v = (i < NN) ? g_deg[i] : 0;
        sh[tid] = v;
        __syncthreads();
        for (int off = 1; off < 1024; off <<= 1) {
            int t = (tid >= off) ? sh[tid - off] : 0;
            __syncthreads();
            sh[tid] += t;
            __syncthreads();
        }
        if (i < NN) {
            int incl = sh[tid];
            g_row[i + 1]  = carry + incl;
            g_cursor[i]   = carry + incl - v;
        }
        __syncthreads();
        if (tid == 0) carry += sh[1023];
        __syncthreads();
    }
}

__global__ void scatter_kernel() {
    int t = blockIdx.x * blockDim.x + threadIdx.x;
    if (t >= NT) return;
    int d = g_edst[t];
    int pos = atomicAdd(&g_cursor[d], 1);
    g_csr_src[pos] = g_esrc[t];
}

// ---------------- SGEMM 128x128, BK=8, 8x8/thread, double-buffered ----------
// C[M,Nn] = A[M,K] @ B[K,Nn], all row-major.
// VEC path requires K%8==0 and Nn%4==0 (float4 global loads).
template <bool VEC>
__global__ __launch_bounds__(256) void sgemm128_kernel(
    const float* __restrict__ A, const float* __restrict__ B,
    float* __restrict__ C, int M, int K, int Nn) {
    __shared__ float As[2][8][128];
    __shared__ float Bs[2][8][128];
    const int tid = threadIdx.x;
    const int tx = tid & 15;         // col group 0..15
    const int ty = tid >> 4;         // row group 0..15
    const int tileM = blockIdx.y * 128;
    const int tileN = blockIdx.x * 128;

    // A load: 128 rows x 8 k -> 256 float4 (2 per row, K-contig)
    const int aRow = tid >> 1;           // 0..127
    const int aCol = (tid & 1) * 4;      // 0 or 4
    // B load: 8 k x 128 n -> 256 float4 (N-contig)
    const int bRow = tid >> 5;           // 0..7
    const int bCol = (tid & 31) * 4;     // 0..124

    const int gmA = tileM + aRow;
    const int nk = (K + 7) / 8;

    float a0, a1, a2, a3, b0, b1, b2, b3;

    // ---- prologue: load tile 0 into regs ----
    {
        const int k0 = 0;
        if (VEC) {
            if (gmA < M) {
                float4 v = *reinterpret_cast<const float4*>(&A[(size_t)gmA * K + k0 + aCol]);
                a0 = v.x; a1 = v.y; a2 = v.z; a3 = v.w;
            } else { a0 = a1 = a2 = a3 = 0.f; }
            int gk = k0 + bRow;
            float4 v = *reinterpret_cast<const float4*>(&B[(size_t)gk * Nn + tileN + bCol]);
            b0 = v.x; b1 = v.y; b2 = v.z; b3 = v.w;
        } else {
            a0 = a1 = a2 = a3 = 0.f;
            if (gmA < M) {
                const float* ap = &A[(size_t)gmA * K];
                if (k0 + aCol + 0 < K) a0 = ap[k0 + aCol + 0];
                if (k0 + aCol + 1 < K) a1 = ap[k0 + aCol + 1];
                if (k0 + aCol + 2 < K) a2 = ap[k0 + aCol + 2];
                if (k0 + aCol + 3 < K) a3 = ap[k0 + aCol + 3];
            }
            b0 = b1 = b2 = b3 = 0.f;
            int gk = k0 + bRow;
            if (gk < K) {
                const float* bp = &B[(size_t)gk * Nn];
                if (tileN + bCol + 0 < Nn) b0 = bp[tileN + bCol + 0];
                if (tileN + bCol + 1 < Nn) b1 = bp[tileN + bCol + 1];
                if (tileN + bCol + 2 < Nn) b2 = bp[tileN + bCol + 2];
                if (tileN + bCol + 3 < Nn) b3 = bp[tileN + bCol + 3];
            }
        }
        As[0][aCol + 0][aRow] = a0;
        As[0][aCol + 1][aRow] = a1;
        As[0][aCol + 2][aRow] = a2;
        As[0][aCol + 3][aRow] = a3;
        Bs[0][bRow][bCol + 0] = b0;
        Bs[0][bRow][bCol + 1] = b1;
        Bs[0][bRow][bCol + 2] = b2;
        Bs[0][bRow][bCol + 3] = b3;
    }
    __syncthreads();

    float acc[2][2][4][4] = {};

    for (int t = 0; t < nk; t++) {
        const int cur = t & 1;
        const bool more = (t + 1 < nk);
        // ---- prefetch next tile into registers ----
        if (more) {
            const int k0 = (t + 1) * 8;
            if (VEC) {
                if (gmA < M) {
                    float4 v = *reinterpret_cast<const float4*>(&A[(size_t)gmA * K + k0 + aCol]);
                    a0 = v.x; a1 = v.y; a2 = v.z; a3 = v.w;
                } else { a0 = a1 = a2 = a3 = 0.f; }
                int gk = k0 + bRow;
                float4 v = *reinterpret_cast<const float4*>(&B[(size_t)gk * Nn + tileN + bCol]);
                b0 = v.x; b1 = v.y; b2 = v.z; b3 = v.w;
            } else {
                a0 = a1 = a2 = a3 = 0.f;
                if (gmA < M) {
                    const float* ap = &A[(size_t)gmA * K];
                    if (k0 + aCol + 0 < K) a0 = ap[k0 + aCol + 0];
                    if (k0 + aCol + 1 < K) a1 = ap[k0 + aCol + 1];
                    if (k0 + aCol + 2 < K) a2 = ap[k0 + aCol + 2];
                    if (k0 + aCol + 3 < K) a3 = ap[k0 + aCol + 3];
                }
                b0 = b1 = b2 = b3 = 0.f;
                int gk = k0 + bRow;
                if (gk < K) {
                    const float* bp = &B[(size_t)gk * Nn];
                    if (tileN + bCol + 0 < Nn) b0 = bp[tileN + bCol + 0];
                    if (tileN + bCol + 1 < Nn) b1 = bp[tileN + bCol + 1];
                    if (tileN + bCol + 2 < Nn) b2 = bp[tileN + bCol + 2];
                    if (tileN + bCol + 3 < Nn) b3 = bp[tileN + bCol + 3];
                }
            }
        }
        // ---- compute on current buffer ----
#pragma unroll
        for (int k = 0; k < 8; k++) {
            float av[8], bv[8];
            float4 va0 = *reinterpret_cast<const float4*>(&As[cur][k][ty * 4]);
            float4 va1 = *reinterpret_cast<const float4*>(&As[cur][k][64 + ty * 4]);
            float4 vb0 = *reinterpret_cast<const float4*>(&Bs[cur][k][tx * 4]);
            float4 vb1 = *reinterpret_cast<const float4*>(&Bs[cur][k][64 + tx * 4]);
            av[0] = va0.x; av[1] = va0.y; av[2] = va0.z; av[3] = va0.w;
            av[4] = va1.x; av[5] = va1.y; av[6] = va1.z; av[7] = va1.w;
            bv[0] = vb0.x; bv[1] = vb0.y; bv[2] = vb0.z; bv[3] = vb0.w;
            bv[4] = vb1.x; bv[5] = vb1.y; bv[6] = vb1.z; bv[7] = vb1.w;
#pragma unroll
            for (int i = 0; i < 8; i++)
#pragma unroll
                for (int j = 0; j < 8; j++)
                    acc[i >> 2][j >> 2][i & 3][j & 3] += av[i] * bv[j];
        }
        // ---- stage next tile into the other buffer ----
        if (more) {
            const int nxt = cur ^ 1;
            As[nxt][aCol + 0][aRow] = a0;
            As[nxt][aCol + 1][aRow] = a1;
            As[nxt][aCol + 2][aRow] = a2;
            As[nxt][aCol + 3][aRow] = a3;
            Bs[nxt][bRow][bCol + 0] = b0;
            Bs[nxt][bRow][bCol + 1] = b1;
            Bs[nxt][bRow][bCol + 2] = b2;
            Bs[nxt][bRow][bCol + 3] = b3;
            __syncthreads();
        }
    }

    // ---- epilogue ----
#pragma unroll
    for (int qi = 0; qi < 2; qi++)
#pragma unroll
        for (int i = 0; i < 4; i++) {
            int gm = tileM + qi * 64 + ty * 4 + i;
            if (gm >= M) continue;
            float* crow = &C[(size_t)gm * Nn];
#pragma unroll
            for (int qj = 0; qj < 2; qj++)
#pragma unroll
                for (int j = 0; j < 4; j++) {
                    int gn = tileN + qj * 64 + tx * 4 + j;
                    if (gn < Nn) crow[gn] = acc[qi][qj][i][j];
                }
        }
}

// ---------------- per-node attention logits ---------------------------------
__global__ void compute_alpha_kernel(const float* __restrict__ xl,
                                     const float* __restrict__ a_src,
                                     const float* __restrict__ a_dst,
                                     int H, int C) {
    int n = blockIdx.x;
    int h = threadIdx.x >> 5;
    int lane = threadIdx.x & 31;
    const float* xr = xl + ((size_t)n * H + h) * C;
    float ss = 0.f, sd = 0.f;
    for (int c = lane; c < C; c += 32) {
        float v = xr[c];
        ss += v * a_src[h * C + c];
        sd += v * a_dst[h * C + c];
    }
#pragma unroll
    for (int off = 16; off > 0; off >>= 1) {
        ss += __shfl_down_sync(0xffffffffu, ss, off);
        sd += __shfl_down_sync(0xffffffffu, sd, off);
    }
    if (lane == 0) {
        g_asrc[n * H + h] = ss;
        g_adst[n * H + h] = sd;
    }
}

// ---------------- softmax-aggregate per (dst, head) --------------------------
__global__ void gat_aggregate_kernel(const float* __restrict__ xl,
                                     float* __restrict__ out, int H, int C) {
    int d = blockIdx.x, h = blockIdx.y;
    int tid = threadIdx.x;
    int r0 = g_row[d], r1 = g_row[d + 1];
    float adv = g_adst[d * H + h];

    __shared__ float smax[256];
    float mx = -1e30f;
    for (int j = r0 + tid; j < r1; j += blockDim.x)
        mx = fmaxf(mx, g_asrc[g_csr_src[j] * H + h]);
    smax[tid] = mx;
    __syncthreads();
    for (int s = blockDim.x >> 1; s > 0; s >>= 1) {
        if (tid < s) smax[tid] = fmaxf(smax[tid], smax[tid + s]);
        __syncthreads();
    }
    float m = smax[0] + adv;
    m = (m > 0.f) ? m : 0.2f * m;  // leaky relu (monotonic, commutes with max)

    float acc = 0.f, denom = 0.f;
    for (int j = r0; j < r1; j++) {
        int s = g_csr_src[j];
        float e = g_asrc[s * H + h] + adv;
        e = (e > 0.f) ? e : 0.2f * e;
        float w = __expf(e - m);
        denom += w;
        if (tid < C) acc += w * xl[((size_t)s * H + h) * C + tid];
    }
    if (tid < C)
        out[((size_t)d * H + h) * C + tid] = acc / (denom + 1e-16f);
}

// ---------------- fused add-skip + layernorm + elu ---------------------------
__global__ __launch_bounds__(256) void ln_elu_kernel(
    const float* __restrict__ agg, const float* __restrict__ b,
    const float* __restrict__ skip, const float* __restrict__ skipb,
    const float* __restrict__ g, const float* __restrict__ beta,
    float* __restrict__ out) {
    int row = blockIdx.x;
    int tid = threadIdx.x;
    const size_t base = (size_t)row * 1024;
    float pre[4];
    float sum = 0.f;
#pragma unroll
    for (int k = 0; k < 4; k++) {
        int i = k * 256 + tid;
        pre[k] = agg[base + i] + b[i] + skip[base + i] + skipb[i];
        sum += pre[k];
    }
    __shared__ float red[256];
    red[tid] = sum;
    __syncthreads();
    for (int s = 128; s > 0; s >>= 1) {
        if (tid < s) red[tid] += red[tid + s];
        __syncthreads();
    }
    float mu = red[0] * (1.f / 1024.f);
    __syncthreads();
    float sq = 0.f;
#pragma unroll
    for (int k = 0; k < 4; k++) {
        float dlt = pre[k] - mu;
        sq += dlt * dlt;
    }
    red[tid] = sq;
    __syncthreads();
    for (int s = 128; s > 0; s >>= 1) {
        if (tid < s) red[tid] += red[tid + s];
        __syncthreads();
    }
    float rstd = rsqrtf(red[0] * (1.f / 1024.f) + 1e-5f);
#pragma unroll
    for (int k = 0; k < 4; k++) {
        int i = k * 256 + tid;
        float v = (pre[k] - mu) * rstd * g[i] + beta[i];
        out[base + i] = (v > 0.f) ? v : expm1f(v);  // elu
    }
}

// ---------------- final head-mean + bias -------------------------------------
__global__ void head_mean_kernel(const float* __restrict__ agg,
                                 const float* __restrict__ b3,
                                 float* __restrict__ out) {
    int idx = blockIdx.x * blockDim.x + threadIdx.x;
    if (idx >= NN * 121) return;
    int n = idx / 121, c = idx % 121;
    float s = 0.f;
#pragma unroll
    for (int h = 0; h < 6; h++) s += agg[((size_t)n * 6 + h) * 121 + c];
    out[idx] = s * (1.f / 6.f) + b3[c];
}

// ---------------- host orchestration -----------------------------------------
static void run_sgemm(const float* A, const float* B, float* C, int M, int K, int Nn) {
    dim3 grid((Nn + 127) / 128, (M + 127) / 128);
    if ((K % 8 == 0) && (Nn % 4 == 0))
        sgemm128_kernel<true><<<grid, 256>>>(A, B, C, M, K, Nn);
    else
        sgemm128_kernel<false><<<grid, 256>>>(A, B, C, M, K, Nn);
}

extern "C" void kernel_launch(void* const* d_in, const int* in_sizes, int n_in,
                              void* d_out, int out_size) {
    const float* x      = (const float*)d_in[0];
    const void*  ei     = d_in[1];
    const float* W1     = (const float*)d_in[2];
    const float* a_src1 = (const float*)d_in[3];
    const float* a_dst1 = (const float*)d_in[4];
    const float* b1     = (const float*)d_in[5];
    const float* W2     = (const float*)d_in[6];
    const float* a_src2 = (const float*)d_in[7];
    const float* a_dst2 = (const float*)d_in[8];
    const float* b2     = (const float*)d_in[9];
    const float* W3     = (const float*)d_in[10];
    const float* a_src3 = (const float*)d_in[11];
    const float* a_dst3 = (const float*)d_in[12];
    const float* b3     = (const float*)d_in[13];
    const float* skipW1 = (const float*)d_in[14];
    const float* skipb1 = (const float*)d_in[15];
    const float* skipW2 = (const float*)d_in[16];
    const float* skipb2 = (const float*)d_in[17];
    const float* g1     = (const float*)d_in[18];
    const float* beta1  = (const float*)d_in[19];
    const float* g2     = (const float*)d_in[20];
    const float* beta2  = (const float*)d_in[21];
    float* out = (float*)d_out;

    float *p_xl, *p_skip, *p_agg, *p_h;
    cudaGetSymbolAddress((void**)&p_xl, g_xl);
    cudaGetSymbolAddress((void**)&p_skip, g_skip);
    cudaGetSymbolAddress((void**)&p_agg, g_agg);
    cudaGetSymbolAddress((void**)&p_h, g_h);

    // ---- CSR build (edges shared by all 3 layers) ----
    detect_dtype_kernel<<<1, 32>>>((const int*)ei);
    zero_deg_kernel<<<(NN + 255) / 256, 256>>>();
    build_edges_kernel<<<(NT + 255) / 256, 256>>>(ei);
    scan_kernel<<<1, 1024>>>();
    scatter_kernel<<<(NT + 255) / 256, 256>>>();

    // ---- Layer 1: GATConv(50 -> 256, H=4, concat) ----
    run_sgemm(x, W1, p_xl, NN, 50, 1024);
    run_sgemm(x, skipW1, p_skip, NN, 50, 1024);
    compute_alpha_kernel<<<NN, 4 * 32>>>(p_xl, a_src1, a_dst1, 4, 256);
    gat_aggregate_kernel<<<dim3(NN, 4), 256>>>(p_xl, p_agg, 4, 256);
    ln_elu_kernel<<<NN, 256>>>(p_agg, b1, p_skip, skipb1, g1, beta1, p_h);

    // ---- Layer 2: GATConv(1024 -> 256, H=4, concat) ----
    run_sgemm(p_h, W2, p_xl, NN, 1024, 1024);
    run_sgemm(p_h, skipW2, p_skip, NN, 1024, 1024);
    compute_alpha_kernel<<<NN, 4 * 32>>>(p_xl, a_src2, a_dst2, 4, 256);
    gat_aggregate_kernel<<<dim3(NN, 4), 256>>>(p_xl, p_agg, 4, 256);
    ln_elu_kernel<<<NN, 256>>>(p_agg, b2, p_skip, skipb2, g2, beta2, p_h);

    // ---- Layer 3: GATConv(1024 -> 121, H=6, mean) ----
    run_sgemm(p_h, W3, p_xl, NN, 1024, 726);
    compute_alpha_kernel<<<NN, 6 * 32>>>(p_xl, a_src3, a_dst3, 6, 121);
    gat_aggregate_kernel<<<dim3(NN, 6), 128>>>(p_xl, p_agg, 6, 121);
    head_mean_kernel<<<(NN * 121 + 255) / 256, 256>>>(p_agg, b3, out);
}

// round 4
// speedup vs baseline: 1.9328x; 1.4233x over previous
#include <cuda_runtime.h>
#include <cuda_bf16.h>
#include <cstdint>

#define NN 20000
#define NE 320000
#define NT (NE + NN)

// ---------------- scratch (device globals; no allocations allowed) ----------
__device__ float g_xl[(size_t)NN * 1024];
__device__ float g_skip[(size_t)NN * 1024];
__device__ float g_agg[(size_t)NN * 1024];
__device__ float g_h[(size_t)NN * 1024];
__device__ float g_asrc[NN * 6];
__device__ float g_adst[NN * 6];
__device__ int   g_deg[NN];
__device__ int   g_row[NN + 1];
__device__ int   g_cursor[NN];
__device__ int   g_esrc[NT];
__device__ int   g_edst[NT];
__device__ int   g_csr_src[NT];
__device__ int   g_is64;

// ---------------- edge dtype detection --------------------------------------
__global__ void detect_dtype_kernel(const int* __restrict__ w) {
    if (threadIdx.x == 0) {
        int nz = 0;
        for (int i = 1; i < 2048; i += 2) nz += (w[i] != 0);
        g_is64 = (nz == 0) ? 1 : 0;
    }
}

// ---------------- graph construction ----------------------------------------
__global__ void zero_deg_kernel() {
    int i = blockIdx.x * blockDim.x + threadIdx.x;
    if (i < NN) g_deg[i] = 0;
}

__global__ void build_edges_kernel(const void* __restrict__ ei) {
    int t = blockIdx.x * blockDim.x + threadIdx.x;
    if (t >= NT) return;
    int s, d;
    if (t < NE) {
        if (g_is64) {
            const long long* p = (const long long*)ei;
            s = (int)p[t];
            d = (int)p[NE + t];
        } else {
            const int* p = (const int*)ei;
            s = p[t];
            d = p[NE + t];
        }
        s = min(max(s, 0), NN - 1);
        d = min(max(d, 0), NN - 1);
    } else {
        s = d = t - NE;  // self loop
    }
    g_esrc[t] = s;
    g_edst[t] = d;
    atomicAdd(&g_deg[d], 1);
}

__global__ void scan_kernel() {
    __shared__ int sh[1024];
    __shared__ int carry;
    int tid = threadIdx.x;
    if (tid == 0) { carry = 0; g_row[0] = 0; }
    __syncthreads();
    for (int base = 0; base < NN; base += 1024) {
        int i = base + tid;
        int v = (i < NN) ? g_deg[i] : 0;
        sh[tid] = v;
        __syncthreads();
        for (int off = 1; off < 1024; off <<= 1) {
            int t = (tid >= off) ? sh[tid - off] : 0;
            __syncthreads();
            sh[tid] += t;
            __syncthreads();
        }
        if (i < NN) {
            int incl = sh[tid];
            g_row[i + 1]  = carry + incl;
            g_cursor[i]   = carry + incl - v;
        }
        __syncthreads();
        if (tid == 0) carry += sh[1023];
        __syncthreads();
    }
}

__global__ void scatter_kernel() {
    int t = blockIdx.x * blockDim.x + threadIdx.x;
    if (t >= NT) return;
    int d = g_edst[t];
    int pos = atomicAdd(&g_cursor[d], 1);
    g_csr_src[pos] = g_esrc[t];
}

// ============================================================================
// bf16x3 tensor-core GEMM: C[M,Nn] = A[M,K] @ B[K,Nn] (fp32 in/out)
// A = A_hi + A_lo (bf16 each); C = Ahi*Bhi + Ahi*Blo + Alo*Bhi (fp32 accum).
// CTA tile 128x128, BK=32. 8 warps in 2x4 -> warp tile 64x32 (4x4 m16n8k16).
// ============================================================================
#define GBM 128
#define GBN 128
#define GBK 32
#define AW  20            // padded words per A smem row (8 data + 12 pad)
#define BW  136           // padded words per B smem packed-k row (128 data + 8)
#define A_P_STRIDE (128 * AW)          // 2560 words per (hi|lo) plane
#define B_P_STRIDE (16 * BW)           // 2176 words per plane
#define BUF_WORDS  (2 * A_P_STRIDE + 2 * B_P_STRIDE)   // 9472
#define GEMM_SMEM_BYTES (2 * BUF_WORDS * 4)            // 75776

__device__ __forceinline__ void packpair(float x0, float x1,
                                         uint32_t& hw, uint32_t& lw) {
    uint32_t b0 = __float_as_uint(x0), b1 = __float_as_uint(x1);
    uint32_t h0 = b0 & 0xFFFF0000u, h1 = b1 & 0xFFFF0000u;
    float l0 = x0 - __uint_as_float(h0);
    float l1 = x1 - __uint_as_float(h1);
    __nv_bfloat16 lb0 = __float2bfloat16(l0);
    __nv_bfloat16 lb1 = __float2bfloat16(l1);
    uint16_t u0 = *reinterpret_cast<uint16_t*>(&lb0);
    uint16_t u1 = *reinterpret_cast<uint16_t*>(&lb1);
    hw = (h0 >> 16) | h1;
    lw = (uint32_t)u0 | ((uint32_t)u1 << 16);
}

__device__ __forceinline__ void mma_bf16(float* c, const uint32_t* a,
                                         const uint32_t* b) {
    asm volatile(
        "mma.sync.aligned.m16n8k16.row.col.f32.bf16.bf16.f32 "
        "{%0,%1,%2,%3},{%4,%5,%6,%7},{%8,%9},{%0,%1,%2,%3};\n"
        : "+f"(c[0]), "+f"(c[1]), "+f"(c[2]), "+f"(c[3])
        : "r"(a[0]), "r"(a[1]), "r"(a[2]), "r"(a[3]), "r"(b[0]), "r"(b[1]));
}

template <bool VECA, bool VECB>
__global__ __launch_bounds__(256) void mma_gemm_kernel(
    const float* __restrict__ A, const float* __restrict__ B,
    float* __restrict__ C, int M, int K, int Nn) {
    extern __shared__ uint32_t sm[];
    const int tid  = threadIdx.x;
    const int warp = tid >> 5, lane = tid & 31;
    const int group = lane >> 2, tg = lane & 3;
    const int wM = (warp >> 2) * 64;   // 0 / 64
    const int wN = (warp & 3) * 32;    // 0..96
    const int tileM = blockIdx.y * GBM;
    const int tileN = blockIdx.x * GBN;
    const int nkt = (K + GBK - 1) / GBK;

    // A loader: thread covers row aRow, k-offsets fBase..fBase+15 (4 float4)
    const int aRow  = tid >> 1;
    const int fBase = (tid & 1) * 16;
    const int gmA   = tileM + aRow;

    float stA[16];
    float stB[16];   // 2 tasks x (row k, row k+1) x 4 n

    // ---------------- load tile kt into staging regs ----------------
    auto loadTile = [&](int kt) {
        const int kB = kt * GBK;
        // ---- A: 16 floats ----
        if (VECA) {
            if (gmA < M) {
                const float* ap = &A[(size_t)gmA * K + kB + fBase];
#pragma unroll
                for (int i = 0; i < 4; i++) {
                    float4 v = *reinterpret_cast<const float4*>(ap + i * 4);
                    stA[i * 4 + 0] = v.x; stA[i * 4 + 1] = v.y;
                    stA[i * 4 + 2] = v.z; stA[i * 4 + 3] = v.w;
                }
            } else {
#pragma unroll
                for (int i = 0; i < 16; i++) stA[i] = 0.f;
            }
        } else {
            const float* ap = (gmA < M) ? &A[(size_t)gmA * K] : nullptr;
#pragma unroll
            for (int i = 0; i < 16; i++) {
                int k = kB + fBase + i;
                stA[i] = (ap && k < K) ? ap[k] : 0.f;
            }
        }
        // ---- B: 2 tasks, each packed-row kp covering n..n+3 over rows (k,k+1)
#pragma unroll
        for (int it = 0; it < 2; it++) {
            int task = tid + it * 256;
            int kp = task >> 5, ng = task & 31;
            int n = ng * 4;
            int gk0 = kB + kp * 2, gk1 = gk0 + 1;
            float r0[4] = {0.f, 0.f, 0.f, 0.f}, r1[4] = {0.f, 0.f, 0.f, 0.f};
            if (VECB) {
                if (gk0 < K) {
                    float4 v = *reinterpret_cast<const float4*>(
                        &B[(size_t)gk0 * Nn + tileN + n]);
                    r0[0] = v.x; r0[1] = v.y; r0[2] = v.z; r0[3] = v.w;
                }
                if (gk1 < K) {
                    float4 v = *reinterpret_cast<const float4*>(
                        &B[(size_t)gk1 * Nn + tileN + n]);
                    r1[0] = v.x; r1[1] = v.y; r1[2] = v.z; r1[3] = v.w;
                }
            } else {
#pragma unroll
                for (int j = 0; j < 4; j++) {
                    int gn = tileN + n + j;
                    if (gn < Nn) {
                        if (gk0 < K) r0[j] = B[(size_t)gk0 * Nn + gn];
                        if (gk1 < K) r1[j] = B[(size_t)gk1 * Nn + gn];
                    }
                }
            }
#pragma unroll
            for (int j = 0; j < 4; j++) {
                stB[it * 8 + j]     = r0[j];
                stB[it * 8 + 4 + j] = r1[j];
            }
        }
    };

    // ---------------- convert + store staging regs into smem buffer ----------
    auto storeTile = [&](int buf) {
        uint32_t* As_ = sm + buf * BUF_WORDS;
        uint32_t* Bs_ = sm + buf * BUF_WORDS + 2 * A_P_STRIDE;
        // A: 16 floats -> 8 packed words at row aRow, word offsets fBase/2 ..
#pragma unroll
        for (int i = 0; i < 8; i++) {
            uint32_t hw, lw;
            packpair(stA[i * 2], stA[i * 2 + 1], hw, lw);
            int w = (fBase >> 1) + i;
            As_[aRow * AW + w] = hw;
            As_[A_P_STRIDE + aRow * AW + w] = lw;
        }
        // B
#pragma unroll
        for (int it = 0; it < 2; it++) {
            int task = tid + it * 256;
            int kp = task >> 5, ng = task & 31;
            int n = ng * 4;
#pragma unroll
            for (int j = 0; j < 4; j++) {
                uint32_t hw, lw;
                packpair(stB[it * 8 + j], stB[it * 8 + 4 + j], hw, lw);
                Bs_[kp * BW + n + j] = hw;
                Bs_[B_P_STRIDE + kp * BW + n + j] = lw;
            }
        }
    };

    float acc[4][4][4] = {};

    loadTile(0);
    storeTile(0);
    __syncthreads();

    for (int t = 0; t < nkt; t++) {
        const int cur = t & 1;
        const bool more = (t + 1 < nkt);
        if (more) loadTile(t + 1);

        const uint32_t* As_ = sm + cur * BUF_WORDS;
        const uint32_t* Bs_ = sm + cur * BUF_WORDS + 2 * A_P_STRIDE;
#pragma unroll
        for (int ks = 0; ks < 2; ks++) {
            const int kb2 = ks * 8;
            uint32_t afr[4][2][4];
#pragma unroll
            for (int i = 0; i < 4; i++) {
                int row = wM + i * 16 + group;
#pragma unroll
                for (int p = 0; p < 2; p++) {
                    const uint32_t* Ap = As_ + p * A_P_STRIDE;
                    afr[i][p][0] = Ap[row * AW + kb2 + tg];
                    afr[i][p][1] = Ap[(row + 8) * AW + kb2 + tg];
                    afr[i][p][2] = Ap[row * AW + kb2 + 4 + tg];
                    afr[i][p][3] = Ap[(row + 8) * AW + kb2 + 4 + tg];
                }
            }
            uint32_t bfr[4][2][2];
#pragma unroll
            for (int j = 0; j < 4; j++) {
                int n = wN + j * 8 + group;
#pragma unroll
                for (int p = 0; p < 2; p++) {
                    const uint32_t* Bp = Bs_ + p * B_P_STRIDE;
                    bfr[j][p][0] = Bp[(kb2 + tg) * BW + n];
                    bfr[j][p][1] = Bp[(kb2 + 4 + tg) * BW + n];
                }
            }
#pragma unroll
            for (int i = 0; i < 4; i++)
#pragma unroll
                for (int j = 0; j < 4; j++) {
                    mma_bf16(acc[i][j], afr[i][0], bfr[j][0]);  // hi*hi
                    mma_bf16(acc[i][j], afr[i][0], bfr[j][1]);  // hi*lo
                    mma_bf16(acc[i][j], afr[i][1], bfr[j][0]);  // lo*hi
                }
        }
        if (more) {
            storeTile(cur ^ 1);
            __syncthreads();
        }
    }

    // ---------------- epilogue ----------------
#pragma unroll
    for (int i = 0; i < 4; i++) {
        int row0 = tileM + wM + i * 16 + group;
#pragma unroll
        for (int j = 0; j < 4; j++) {
            int col0 = tileN + wN + j * 8 + tg * 2;
            if (row0 < M) {
                if (col0 < Nn)     C[(size_t)row0 * Nn + col0]     = acc[i][j][0];
                if (col0 + 1 < Nn) C[(size_t)row0 * Nn + col0 + 1] = acc[i][j][1];
            }
            if (row0 + 8 < M) {
                if (col0 < Nn)     C[(size_t)(row0 + 8) * Nn + col0]     = acc[i][j][2];
                if (col0 + 1 < Nn) C[(size_t)(row0 + 8) * Nn + col0 + 1] = acc[i][j][3];
            }
        }
    }
}

// ---------------- per-node attention logits ---------------------------------
__global__ void compute_alpha_kernel(const float* __restrict__ xl,
                                     const float* __restrict__ a_src,
                                     const float* __restrict__ a_dst,
                                     int H, int C) {
    int n = blockIdx.x;
    int h = threadIdx.x >> 5;
    int lane = threadIdx.x & 31;
    const float* xr = xl + ((size_t)n * H + h) * C;
    float ss = 0.f, sd = 0.f;
    for (int c = lane; c < C; c += 32) {
        float v = xr[c];
        ss += v * a_src[h * C + c];
        sd += v * a_dst[h * C + c];
    }
#pragma unroll
    for (int off = 16; off > 0; off >>= 1) {
        ss += __shfl_down_sync(0xffffffffu, ss, off);
        sd += __shfl_down_sync(0xffffffffu, sd, off);
    }
    if (lane == 0) {
        g_asrc[n * H + h] = ss;
        g_adst[n * H + h] = sd;
    }
}

// ---------------- softmax-aggregate per (dst, head) --------------------------
__global__ void gat_aggregate_kernel(const float* __restrict__ xl,
                                     float* __restrict__ out, int H, int C) {
    int d = blockIdx.x, h = blockIdx.y;
    int tid = threadIdx.x;
    int r0 = g_row[d], r1 = g_row[d + 1];
    float adv = g_adst[d * H + h];

    __shared__ float smax[256];
    float mx = -1e30f;
    for (int j = r0 + tid; j < r1; j += blockDim.x)
        mx = fmaxf(mx, g_asrc[g_csr_src[j] * H + h]);
    smax[tid] = mx;
    __syncthreads();
    for (int s = blockDim.x >> 1; s > 0; s >>= 1) {
        if (tid < s) smax[tid] = fmaxf(smax[tid], smax[tid + s]);
        __syncthreads();
    }
    float m = smax[0] + adv;
    m = (m > 0.f) ? m : 0.2f * m;  // leaky relu (monotonic, commutes with max)

    float acc = 0.f, denom = 0.f;
    for (int j = r0; j < r1; j++) {
        int s = g_csr_src[j];
        float e = g_asrc[s * H + h] + adv;
        e = (e > 0.f) ? e : 0.2f * e;
        float w = __expf(e - m);
        denom += w;
        if (tid < C) acc += w * xl[((size_t)s * H + h) * C + tid];
    }
    if (tid < C)
        out[((size_t)d * H + h) * C + tid] = acc / (denom + 1e-16f);
}

// ---------------- fused add-skip + layernorm + elu ---------------------------
__global__ __launch_bounds__(256) void ln_elu_kernel(
    const float* __restrict__ agg, const float* __restrict__ b,
    const float* __restrict__ skip, const float* __restrict__ skipb,
    const float* __restrict__ g, const float* __restrict__ beta,
    float* __restrict__ out) {
    int row = blockIdx.x;
    int tid = threadIdx.x;
    const size_t base = (size_t)row * 1024;
    float pre[4];
    float sum = 0.f;
#pragma unroll
    for (int k = 0; k < 4; k++) {
        int i = k * 256 + tid;
        pre[k] = agg[base + i] + b[i] + skip[base + i] + skipb[i];
        sum += pre[k];
    }
    __shared__ float red[256];
    red[tid] = sum;
    __syncthreads();
    for (int s = 128; s > 0; s >>= 1) {
        if (tid < s) red[tid] += red[tid + s];
        __syncthreads();
    }
    float mu = red[0] * (1.f / 1024.f);
    __syncthreads();
    float sq = 0.f;
#pragma unroll
    for (int k = 0; k < 4; k++) {
        float dlt = pre[k] - mu;
        sq += dlt * dlt;
    }
    red[tid] = sq;
    __syncthreads();
    for (int s = 128; s > 0; s >>= 1) {
        if (tid < s) red[tid] += red[tid + s];
        __syncthreads();
    }
    float rstd = rsqrtf(red[0] * (1.f / 1024.f) + 1e-5f);
#pragma unroll
    for (int k = 0; k < 4; k++) {
        int i = k * 256 + tid;
        float v = (pre[k] - mu) * rstd * g[i] + beta[i];
        out[base + i] = (v > 0.f) ? v : expm1f(v);  // elu
    }
}

// ---------------- final head-mean + bias -------------------------------------
__global__ void head_mean_kernel(const float* __restrict__ agg,
                                 const float* __restrict__ b3,
                                 float* __restrict__ out) {
    int idx = blockIdx.x * blockDim.x + threadIdx.x;
    if (idx >= NN * 121) return;
    int n = idx / 121, c = idx % 121;
    float s = 0.f;
#pragma unroll
    for (int h = 0; h < 6; h++) s += agg[((size_t)n * 6 + h) * 121 + c];
    out[idx] = s * (1.f / 6.f) + b3[c];
}

// ---------------- host orchestration -----------------------------------------
static void run_gemm(const float* A, const float* B, float* C, int M, int K, int Nn) {
    dim3 grid((Nn + GBN - 1) / GBN, (M + GBM - 1) / GBM);
    bool veca = (K % 32 == 0);
    bool vecb = (Nn % 4 == 0);
    static bool attr_done = false;
    if (!attr_done) {
        cudaFuncSetAttribute(mma_gemm_kernel<true, true>,
                             cudaFuncAttributeMaxDynamicSharedMemorySize, GEMM_SMEM_BYTES);
        cudaFuncSetAttribute(mma_gemm_kernel<true, false>,
                             cudaFuncAttributeMaxDynamicSharedMemorySize, GEMM_SMEM_BYTES);
        cudaFuncSetAttribute(mma_gemm_kernel<false, true>,
                             cudaFuncAttributeMaxDynamicSharedMemorySize, GEMM_SMEM_BYTES);
        cudaFuncSetAttribute(mma_gemm_kernel<false, false>,
                             cudaFuncAttributeMaxDynamicSharedMemorySize, GEMM_SMEM_BYTES);
        attr_done = true;
    }
    if (veca && vecb)
        mma_gemm_kernel<true, true><<<grid, 256, GEMM_SMEM_BYTES>>>(A, B, C, M, K, Nn);
    else if (veca && !vecb)
        mma_gemm_kernel<true, false><<<grid, 256, GEMM_SMEM_BYTES>>>(A, B, C, M, K, Nn);
    else if (!veca && vecb)
        mma_gemm_kernel<false, true><<<grid, 256, GEMM_SMEM_BYTES>>>(A, B, C, M, K, Nn);
    else
        mma_gemm_kernel<false, false><<<grid, 256, GEMM_SMEM_BYTES>>>(A, B, C, M, K, Nn);
}

extern "C" void kernel_launch(void* const* d_in, const int* in_sizes, int n_in,
                              void* d_out, int out_size) {
    const float* x      = (const float*)d_in[0];
    const void*  ei     = d_in[1];
    const float* W1     = (const float*)d_in[2];
    const float* a_src1 = (const float*)d_in[3];
    const float* a_dst1 = (const float*)d_in[4];
    const float* b1     = (const float*)d_in[5];
    const float* W2     = (const float*)d_in[6];
    const float* a_src2 = (const float*)d_in[7];
    const float* a_dst2 = (const float*)d_in[8];
    const float* b2     = (const float*)d_in[9];
    const float* W3     = (const float*)d_in[10];
    const float* a_src3 = (const float*)d_in[11];
    const float* a_dst3 = (const float*)d_in[12];
    const float* b3     = (const float*)d_in[13];
    const float* skipW1 = (const float*)d_in[14];
    const float* skipb1 = (const float*)d_in[15];
    const float* skipW2 = (const float*)d_in[16];
    const float* skipb2 = (const float*)d_in[17];
    const float* g1     = (const float*)d_in[18];
    const float* beta1  = (const float*)d_in[19];
    const float* g2     = (const float*)d_in[20];
    const float* beta2  = (const float*)d_in[21];
    float* out = (float*)d_out;

    float *p_xl, *p_skip, *p_agg, *p_h;
    cudaGetSymbolAddress((void**)&p_xl, g_xl);
    cudaGetSymbolAddress((void**)&p_skip, g_skip);
    cudaGetSymbolAddress((void**)&p_agg, g_agg);
    cudaGetSymbolAddress((void**)&p_h, g_h);

    // ---- CSR build (edges shared by all 3 layers) ----
    detect_dtype_kernel<<<1, 32>>>((const int*)ei);
    zero_deg_kernel<<<(NN + 255) / 256, 256>>>();
    build_edges_kernel<<<(NT + 255) / 256, 256>>>(ei);
    scan_kernel<<<1, 1024>>>();
    scatter_kernel<<<(NT + 255) / 256, 256>>>();

    // ---- Layer 1: GATConv(50 -> 256, H=4, concat) ----
    run_gemm(x, W1, p_xl, NN, 50, 1024);
    run_gemm(x, skipW1, p_skip, NN, 50, 1024);
    compute_alpha_kernel<<<NN, 4 * 32>>>(p_xl, a_src1, a_dst1, 4, 256);
    gat_aggregate_kernel<<<dim3(NN, 4), 256>>>(p_xl, p_agg, 4, 256);
    ln_elu_kernel<<<NN, 256>>>(p_agg, b1, p_skip, skipb1, g1, beta1, p_h);

    // ---- Layer 2: GATConv(1024 -> 256, H=4, concat) ----
    run_gemm(p_h, W2, p_xl, NN, 1024, 1024);
    run_gemm(p_h, skipW2, p_skip, NN, 1024, 1024);
    compute_alpha_kernel<<<NN, 4 * 32>>>(p_xl, a_src2, a_dst2, 4, 256);
    gat_aggregate_kernel<<<dim3(NN, 4), 256>>>(p_xl, p_agg, 4, 256);
    ln_elu_kernel<<<NN, 256>>>(p_agg, b2, p_skip, skipb2, g2, beta2, p_h);

    // ---- Layer 3: GATConv(1024 -> 121, H=6, mean) ----
    run_gemm(p_h, W3, p_xl, NN, 1024, 726);
    compute_alpha_kernel<<<NN, 6 * 32>>>(p_xl, a_src3, a_dst3, 6, 121);
    gat_aggregate_kernel<<<dim3(NN, 6), 128>>>(p_xl, p_agg, 6, 121);
    head_mean_kernel<<<(NN * 121 + 255) / 256, 256>>>(p_agg, b3, out);
}

// round 7
// speedup vs baseline: 2.0870x; 1.0798x over previous
#include <cuda_runtime.h>
#include <cuda_bf16.h>
#include <cstdint>

#define NN 20000
#define MPAD 20096              // NN rounded up to 128
#define NE 320000
#define NT (NE + NN)

// ---------------- scratch (device globals; no allocations allowed) ----------
__device__ float g_xl[(size_t)NN * 1024];
__device__ float g_skip[(size_t)NN * 1024];
__device__ float g_agg[(size_t)NN * 1024];
__device__ float g_h[(size_t)NN * 1024];
__device__ uint32_t g_ah[(size_t)MPAD * 512];   // packed bf16-hi A plane
__device__ uint32_t g_al[(size_t)MPAD * 512];   // packed bf16-lo A plane
__device__ uint32_t g_bh[(size_t)512 * 2048];   // packed bf16-hi B plane
__device__ uint32_t g_bl[(size_t)512 * 2048];   // packed bf16-lo B plane
__device__ float g_asrc[NN * 6];
__device__ float g_adst[NN * 6];
__device__ int   g_deg[NN];
__device__ int   g_row[NN + 1];
__device__ int   g_cursor[NN];
__device__ int   g_esrc[NT];
__device__ int   g_edst[NT];
__device__ int   g_csr_src[NT];
__device__ int   g_is64;

// ---------------- edge dtype detection --------------------------------------
__global__ void detect_dtype_kernel(const int* __restrict__ w) {
    if (threadIdx.x == 0) {
        int nz = 0;
        for (int i = 1; i < 2048; i += 2) nz += (w[i] != 0);
        g_is64 = (nz == 0) ? 1 : 0;
    }
}

// ---------------- graph construction ----------------------------------------
__global__ void zero_deg_kernel() {
    int i = blockIdx.x * blockDim.x + threadIdx.x;
    if (i < NN) g_deg[i] = 0;
}

__global__ void build_edges_kernel(const void* __restrict__ ei) {
    int t = blockIdx.x * blockDim.x + threadIdx.x;
    if (t >= NT) return;
    int s, d;
    if (t < NE) {
        if (g_is64) {
            const long long* p = (const long long*)ei;
            s = (int)p[t];
            d = (int)p[NE + t];
        } else {
            const int* p = (const int*)ei;
            s = p[t];
            d = p[NE + t];
        }
        s = min(max(s, 0), NN - 1);
        d = min(max(d, 0), NN - 1);
    } else {
        s = d = t - NE;  // self loop
    }
    g_esrc[t] = s;
    g_edst[t] = d;
    atomicAdd(&g_deg[d], 1);
}

__global__ void scan_kernel() {
    __shared__ int sh[1024];
    __shared__ int carry;
    int tid = threadIdx.x;
    if (tid == 0) { carry = 0; g_row[0] = 0; }
    __syncthreads();
    for (int base = 0; base < NN; base += 1024) {
        int i = base + tid;
        int v = (i < NN) ? g_deg[i] : 0;
        sh[tid] = v;
        __syncthreads();
        for (int off = 1; off < 1024; off <<= 1) {
            int t = (tid >= off) ? sh[tid - off] : 0;
            __syncthreads();
            sh[tid] += t;
            __syncthreads();
        }
        if (i < NN) {
            int incl = sh[tid];
            g_row[i + 1]  = carry + incl;
            g_cursor[i]   = carry + incl - v;
        }
        __syncthreads();
        if (tid == 0) carry += sh[1023];
        __syncthreads();
    }
}

__global__ void scatter_kernel() {
    int t = blockIdx.x * blockDim.x + threadIdx.x;
    if (t >= NT) return;
    int d = g_edst[t];
    int pos = atomicAdd(&g_cursor[d], 1);
    g_csr_src[pos] = g_esrc[t];
}

// ============================================================================
// hi/lo bf16 pre-conversion
// ============================================================================
__device__ __forceinline__ void packpair(float x0, float x1,
                                         uint32_t& hw, uint32_t& lw) {
    uint32_t b0 = __float_as_uint(x0), b1 = __float_as_uint(x1);
    uint32_t h0 = b0 & 0xFFFF0000u, h1 = b1 & 0xFFFF0000u;
    float l0 = x0 - __uint_as_float(h0);
    float l1 = x1 - __uint_as_float(h1);
    __nv_bfloat16 lb0 = __float2bfloat16(l0);
    __nv_bfloat16 lb1 = __float2bfloat16(l1);
    uint16_t u0 = *reinterpret_cast<uint16_t*>(&lb0);
    uint16_t u1 = *reinterpret_cast<uint16_t*>(&lb1);
    hw = (h0 >> 16) | h1;
    lw = (uint32_t)u0 | ((uint32_t)u1 << 16);
}

// A[M,K] fp32 -> packed word planes g_ah/g_al [MPAD][aStride]; zero pad.
__global__ void cvt_a_kernel(const float* __restrict__ A, int M, int K,
                             int aStride) {
    int t = blockIdx.x * blockDim.x + threadIdx.x;
    if (t >= MPAD * aStride) return;
    int row = t / aStride, kp = t - row * aStride;
    float x0 = 0.f, x1 = 0.f;
    if (row < M) {
        int k0 = kp * 2;
        const float* ap = &A[(size_t)row * K];
        if (k0 < K)     x0 = ap[k0];
        if (k0 + 1 < K) x1 = ap[k0 + 1];
    }
    uint32_t hw, lw;
    packpair(x0, x1, hw, lw);
    g_ah[t] = hw;
    g_al[t] = lw;
}

// Concat(B0[K,N0c], B1[K,N1c]) -> packed k-pair planes g_bh/g_bl [kpHalf][Np].
__global__ void cvt_w_kernel(const float* __restrict__ B0, int N0c,
                             const float* __restrict__ B1, int N1c,
                             int K, int Np, int kpHalf) {
    int t = blockIdx.x * blockDim.x + threadIdx.x;
    if (t >= kpHalf * Np) return;
    int kp = t / Np, n = t - kp * Np;
    int k0 = kp * 2;
    float x0 = 0.f, x1 = 0.f;
    if (n < N0c) {
        if (k0 < K)     x0 = B0[(size_t)k0 * N0c + n];
        if (k0 + 1 < K) x1 = B0[(size_t)(k0 + 1) * N0c + n];
    } else if (B1 != nullptr && n - N0c < N1c) {
        int nn = n - N0c;
        if (k0 < K)     x0 = B1[(size_t)k0 * N1c + nn];
        if (k0 + 1 < K) x1 = B1[(size_t)(k0 + 1) * N1c + nn];
    }
    uint32_t hw, lw;
    packpair(x0, x1, hw, lw);
    g_bh[t] = hw;
    g_bl[t] = lw;
}

// ============================================================================
// bf16x3 tensor-core GEMM, pre-converted operands, cp.async pipeline.
// CTA tile 128x128, BK=32. 8 warps 2x4 -> warp tile 64x32 (4x4 m16n8k16 x3).
// ============================================================================
#define AW  20
#define BW  136
#define A_P_STRIDE (128 * AW)
#define B_P_STRIDE (16 * BW)
#define BUF_WORDS  (2 * A_P_STRIDE + 2 * B_P_STRIDE)
#define GEMM_SMEM_BYTES (2 * BUF_WORDS * 4)

__device__ __forceinline__ void mma_bf16(float* c, const uint32_t* a,
                                         const uint32_t* b) {
    asm volatile(
        "mma.sync.aligned.m16n8k16.row.col.f32.bf16.bf16.f32 "
        "{%0,%1,%2,%3},{%4,%5,%6,%7},{%8,%9},{%0,%1,%2,%3};\n"
        : "+f"(c[0]), "+f"(c[1]), "+f"(c[2]), "+f"(c[3])
        : "r"(a[0]), "r"(a[1]), "r"(a[2]), "r"(a[3]), "r"(b[0]), "r"(b[1]));
}

__device__ __forceinline__ void cp16(uint32_t saddr, const void* g) {
    asm volatile("cp.async.ca.shared.global [%0], [%1], 16;\n"
                 :: "r"(saddr), "l"(g));
}

__global__ __launch_bounds__(256) void mma_gemm_async(
    const uint32_t* __restrict__ Ah, const uint32_t* __restrict__ Al,
    const uint32_t* __restrict__ Bh, const uint32_t* __restrict__ Bl,
    float* __restrict__ C0, float* __restrict__ C1,
    int M, int aStride, int Np, int N0, int N1, int nkt) {
    extern __shared__ uint32_t sm[];
    const int tid  = threadIdx.x;
    const int warp = tid >> 5, lane = tid & 31;
    const int group = lane >> 2, tg = lane & 3;
    const int wM = (warp >> 2) * 64;
    const int wN = (warp & 3) * 32;
    const int tileM = blockIdx.y * 128;
    const int tileN = blockIdx.x * 128;

    // A loader mapping: row, 8-word half per plane
    const int aRow = tid >> 1, aHalf = tid & 1;
    const size_t aGbase = (size_t)(tileM + aRow) * aStride + aHalf * 8;
    const uint32_t aSbase = aRow * AW + aHalf * 8;
    // B loader mapping: kp row, 8-word n chunk
    const int bKp = tid >> 4, bN0 = (tid & 15) * 8;
    const uint32_t bSbase = bKp * BW + bN0;

    auto issue = [&](int kt, int buf) {
        uint32_t* s = sm + buf * BUF_WORDS;
        // A hi/lo
        {
            const uint32_t* gh = Ah + aGbase + kt * 16;
            const uint32_t* gl = Al + aGbase + kt * 16;
            uint32_t sh_ = (uint32_t)__cvta_generic_to_shared(s + aSbase);
            uint32_t sl_ = (uint32_t)__cvta_generic_to_shared(s + A_P_STRIDE + aSbase);
            cp16(sh_, gh); cp16(sh_ + 16, gh + 4);
            cp16(sl_, gl); cp16(sl_ + 16, gl + 4);
        }
        // B hi/lo  (note: tileN offset!)
        {
            const size_t go = (size_t)(kt * 16 + bKp) * Np + tileN + bN0;
            const uint32_t* gh = Bh + go;
            const uint32_t* gl = Bl + go;
            uint32_t* bs = s + 2 * A_P_STRIDE;
            uint32_t sh_ = (uint32_t)__cvta_generic_to_shared(bs + bSbase);
            uint32_t sl_ = (uint32_t)__cvta_generic_to_shared(bs + B_P_STRIDE + bSbase);
            cp16(sh_, gh); cp16(sh_ + 16, gh + 4);
            cp16(sl_, gl); cp16(sl_ + 16, gl + 4);
        }
    };

    float acc[4][4][4] = {};

    issue(0, 0);
    asm volatile("cp.async.commit_group;\n");

    for (int t = 0; t < nkt; t++) {
        const int cur = t & 1;
        const bool more = (t + 1 < nkt);
        if (more) {
            issue(t + 1, cur ^ 1);
            asm volatile("cp.async.commit_group;\n");
            asm volatile("cp.async.wait_group 1;\n");
        } else {
            asm volatile("cp.async.wait_group 0;\n");
        }
        __syncthreads();

        const uint32_t* As_ = sm + cur * BUF_WORDS;
        const uint32_t* Bs_ = sm + cur * BUF_WORDS + 2 * A_P_STRIDE;
#pragma unroll
        for (int ks = 0; ks < 2; ks++) {
            const int kb2 = ks * 8;
            uint32_t afr[4][2][4];
#pragma unroll
            for (int i = 0; i < 4; i++) {
                int row = wM + i * 16 + group;
#pragma unroll
                for (int p = 0; p < 2; p++) {
                    const uint32_t* Ap = As_ + p * A_P_STRIDE;
                    afr[i][p][0] = Ap[row * AW + kb2 + tg];
                    afr[i][p][1] = Ap[(row + 8) * AW + kb2 + tg];
                    afr[i][p][2] = Ap[row * AW + kb2 + 4 + tg];
                    afr[i][p][3] = Ap[(row + 8) * AW + kb2 + 4 + tg];
                }
            }
            uint32_t bfr[4][2][2];
#pragma unroll
            for (int j = 0; j < 4; j++) {
                int n = wN + j * 8 + group;
#pragma unroll
                for (int p = 0; p < 2; p++) {
                    const uint32_t* Bp = Bs_ + p * B_P_STRIDE;
                    bfr[j][p][0] = Bp[(kb2 + tg) * BW + n];
                    bfr[j][p][1] = Bp[(kb2 + 4 + tg) * BW + n];
                }
            }
#pragma unroll
            for (int i = 0; i < 4; i++)
#pragma unroll
                for (int j = 0; j < 4; j++) {
                    mma_bf16(acc[i][j], afr[i][0], bfr[j][0]);  // hi*hi
                    mma_bf16(acc[i][j], afr[i][0], bfr[j][1]);  // hi*lo
                    mma_bf16(acc[i][j], afr[i][1], bfr[j][0]);  // lo*hi
                }
        }
        __syncthreads();
    }

    // ---------------- epilogue: split store into C0 / C1 ----------------
    auto store = [&](int gm, int gn, float v) {
        if (gm >= M) return;
        if (gn < N0) {
            C0[(size_t)gm * N0 + gn] = v;
        } else {
            int n2 = gn - N0;
            if (n2 < N1) C1[(size_t)gm * N1 + n2] = v;
        }
    };
#pragma unroll
    for (int i = 0; i < 4; i++) {
        int row0 = tileM + wM + i * 16 + group;
#pragma unroll
        for (int j = 0; j < 4; j++) {
            int col0 = tileN + wN + j * 8 + tg * 2;
            store(row0,     col0,     acc[i][j][0]);
            store(row0,     col0 + 1, acc[i][j][1]);
            store(row0 + 8, col0,     acc[i][j][2]);
            store(row0 + 8, col0 + 1, acc[i][j][3]);
        }
    }
}

// ---------------- per-node attention logits ---------------------------------
__global__ void compute_alpha_kernel(const float* __restrict__ xl,
                                     const float* __restrict__ a_src,
                                     const float* __restrict__ a_dst,
                                     int H, int C) {
    int n = blockIdx.x;
    int h = threadIdx.x >> 5;
    int lane = threadIdx.x & 31;
    const float* xr = xl + ((size_t)n * H + h) * C;
    float ss = 0.f, sd = 0.f;
    for (int c = lane; c < C; c += 32) {
        float v = xr[c];
        ss += v * a_src[h * C + c];
        sd += v * a_dst[h * C + c];
    }
#pragma unroll
    for (int off = 16; off > 0; off >>= 1) {
        ss += __shfl_down_sync(0xffffffffu, ss, off);
        sd += __shfl_down_sync(0xffffffffu, sd, off);
    }
    if (lane == 0) {
        g_asrc[n * H + h] = ss;
        g_adst[n * H + h] = sd;
    }
}

// ---------------- softmax-aggregate per (dst, head) --------------------------
__global__ void gat_aggregate_kernel(const float* __restrict__ xl,
                                     float* __restrict__ out, int H, int C) {
    int d = blockIdx.x, h = blockIdx.y;
    int tid = threadIdx.x;
    int r0 = g_row[d], r1 = g_row[d + 1];
    float adv = g_adst[d * H + h];

    __shared__ float smax[256];
    float mx = -1e30f;
    for (int j = r0 + tid; j < r1; j += blockDim.x)
        mx = fmaxf(mx, g_asrc[g_csr_src[j] * H + h]);
    smax[tid] = mx;
    __syncthreads();
    for (int s = blockDim.x >> 1; s > 0; s >>= 1) {
        if (tid < s) smax[tid] = fmaxf(smax[tid], smax[tid + s]);
        __syncthreads();
    }
    float m = smax[0] + adv;
    m = (m > 0.f) ? m : 0.2f * m;  // leaky relu (monotonic, commutes with max)

    float acc = 0.f, denom = 0.f;
    for (int j = r0; j < r1; j++) {
        int s = g_csr_src[j];
        float e = g_asrc[s * H + h] + adv;
        e = (e > 0.f) ? e : 0.2f * e;
        float w = __expf(e - m);
        denom += w;
        if (tid < C) acc += w * xl[((size_t)s * H + h) * C + tid];
    }
    if (tid < C)
        out[((size_t)d * H + h) * C + tid] = acc / (denom + 1e-16f);
}

// ---------------- fused add-skip + layernorm + elu ---------------------------
__global__ __launch_bounds__(256) void ln_elu_kernel(
    const float* __restrict__ agg, const float* __restrict__ b,
    const float* __restrict__ skip, const float* __restrict__ skipb,
    const float* __restrict__ g, const float* __restrict__ beta,
    float* __restrict__ out) {
    int row = blockIdx.x;
    int tid = threadIdx.x;
    const size_t base = (size_t)row * 1024;
    float pre[4];
    float sum = 0.f;
#pragma unroll
    for (int k = 0; k < 4; k++) {
        int i = k * 256 + tid;
        pre[k] = agg[base + i] + b[i] + skip[base + i] + skipb[i];
        sum += pre[k];
    }
    __shared__ float red[256];
    red[tid] = sum;
    __syncthreads();
    for (int s = 128; s > 0; s >>= 1) {
        if (tid < s) red[tid] += red[tid + s];
        __syncthreads();
    }
    float mu = red[0] * (1.f / 1024.f);
    __syncthreads();
    float sq = 0.f;
#pragma unroll
    for (int k = 0; k < 4; k++) {
        float dlt = pre[k] - mu;
        sq += dlt * dlt;
    }
    red[tid] = sq;
    __syncthreads();
    for (int s = 128; s > 0; s >>= 1) {
        if (tid < s) red[tid] += red[tid + s];
        __syncthreads();
    }
    float rstd = rsqrtf(red[0] * (1.f / 1024.f) + 1e-5f);
#pragma unroll
    for (int k = 0; k < 4; k++) {
        int i = k * 256 + tid;
        float v = (pre[k] - mu) * rstd * g[i] + beta[i];
        out[base + i] = (v > 0.f) ? v : expm1f(v);  // elu
    }
}

// ---------------- final head-mean + bias -------------------------------------
__global__ void head_mean_kernel(const float* __restrict__ agg,
                                 const float* __restrict__ b3,
                                 float* __restrict__ out) {
    int idx = blockIdx.x * blockDim.x + threadIdx.x;
    if (idx >= NN * 121) return;
    int n = idx / 121, c = idx % 121;
    float s = 0.f;
#pragma unroll
    for (int h = 0; h < 6; h++) s += agg[((size_t)n * 6 + h) * 121 + c];
    out[idx] = s * (1.f / 6.f) + b3[c];
}

// ---------------- host orchestration -----------------------------------------
extern "C" void kernel_launch(void* const* d_in, const int* in_sizes, int n_in,
                              void* d_out, int out_size) {
    const float* x      = (const float*)d_in[0];
    const void*  ei     = d_in[1];
    const float* W1     = (const float*)d_in[2];
    const float* a_src1 = (const float*)d_in[3];
    const float* a_dst1 = (const float*)d_in[4];
    const float* b1     = (const float*)d_in[5];
    const float* W2     = (const float*)d_in[6];
    const float* a_src2 = (const float*)d_in[7];
    const float* a_dst2 = (const float*)d_in[8];
    const float* b2     = (const float*)d_in[9];
    const float* W3     = (const float*)d_in[10];
    const float* a_src3 = (const float*)d_in[11];
    const float* a_dst3 = (const float*)d_in[12];
    const float* b3     = (const float*)d_in[13];
    const float* skipW1 = (const float*)d_in[14];
    const float* skipb1 = (const float*)d_in[15];
    const float* skipW2 = (const float*)d_in[16];
    const float* skipb2 = (const float*)d_in[17];
    const float* g1     = (const float*)d_in[18];
    const float* beta1  = (const float*)d_in[19];
    const float* g2     = (const float*)d_in[20];
    const float* beta2  = (const float*)d_in[21];
    float* out = (float*)d_out;

    float *p_xl, *p_skip, *p_agg, *p_h;
    uint32_t *p_ah, *p_al, *p_bh, *p_bl;
    cudaGetSymbolAddress((void**)&p_xl, g_xl);
    cudaGetSymbolAddress((void**)&p_skip, g_skip);
    cudaGetSymbolAddress((void**)&p_agg, g_agg);
    cudaGetSymbolAddress((void**)&p_h, g_h);
    cudaGetSymbolAddress((void**)&p_ah, g_ah);
    cudaGetSymbolAddress((void**)&p_al, g_al);
    cudaGetSymbolAddress((void**)&p_bh, g_bh);
    cudaGetSymbolAddress((void**)&p_bl, g_bl);

    cudaFuncSetAttribute(mma_gemm_async,
                         cudaFuncAttributeMaxDynamicSharedMemorySize,
                         GEMM_SMEM_BYTES);

    // ---- CSR build (edges shared by all 3 layers) ----
    detect_dtype_kernel<<<1, 32>>>((const int*)ei);
    zero_deg_kernel<<<(NN + 255) / 256, 256>>>();
    build_edges_kernel<<<(NT + 255) / 256, 256>>>(ei);
    scan_kernel<<<1, 1024>>>();
    scatter_kernel<<<(NT + 255) / 256, 256>>>();

    const int gridM = MPAD / 128;   // 157

    // ---- Layer 1: GATConv(50 -> 256, H=4, concat) + skip; K=50 Kpad=64 ----
    {
        const int K = 50, aStride = 32, nkt = 2, Np = 2048;
        cvt_w_kernel<<<((Np * aStride) + 255) / 256, 256>>>(
            W1, 1024, skipW1, 1024, K, Np, aStride);
        cvt_a_kernel<<<((MPAD * aStride) + 255) / 256, 256>>>(x, NN, K, aStride);
        mma_gemm_async<<<dim3(Np / 128, gridM), 256, GEMM_SMEM_BYTES>>>(
            p_ah, p_al, p_bh, p_bl, p_xl, p_skip, NN, aStride, Np, 1024, 1024, nkt);
    }
    compute_alpha_kernel<<<NN, 4 * 32>>>(p_xl, a_src1, a_dst1, 4, 256);
    gat_aggregate_kernel<<<dim3(NN, 4), 256>>>(p_xl, p_agg, 4, 256);
    ln_elu_kernel<<<NN, 256>>>(p_agg, b1, p_skip, skipb1, g1, beta1, p_h);

    // ---- Layer 2: GATConv(1024 -> 256, H=4, concat) + skip ----
    {
        const int K = 1024, aStride = 512, nkt = 32, Np = 2048;
        cvt_w_kernel<<<((Np * aStride) + 255) / 256, 256>>>(
            W2, 1024, skipW2, 1024, K, Np, aStride);
        cvt_a_kernel<<<((MPAD * aStride) + 255) / 256, 256>>>(p_h, NN, K, aStride);
        mma_gemm_async<<<dim3(Np / 128, gridM), 256, GEMM_SMEM_BYTES>>>(
            p_ah, p_al, p_bh, p_bl, p_xl, p_skip, NN, aStride, Np, 1024, 1024, nkt);
    }
    compute_alpha_kernel<<<NN, 4 * 32>>>(p_xl, a_src2, a_dst2, 4, 256);
    gat_aggregate_kernel<<<dim3(NN, 4), 256>>>(p_xl, p_agg, 4, 256);
    ln_elu_kernel<<<NN, 256>>>(p_agg, b2, p_skip, skipb2, g2, beta2, p_h);

    // ---- Layer 3: GATConv(1024 -> 121, H=6, mean); N=726 pad 768 ----
    {
        const int K = 1024, aStride = 512, nkt = 32, Np = 768;
        cvt_w_kernel<<<((Np * aStride) + 255) / 256, 256>>>(
            W3, 726, (const float*)nullptr, 0, K, Np, aStride);
        cvt_a_kernel<<<((MPAD * aStride) + 255) / 256, 256>>>(p_h, NN, K, aStride);
        mma_gemm_async<<<dim3(Np / 128, gridM), 256, GEMM_SMEM_BYTES>>>(
            p_ah, p_al, p_bh, p_bl, p_xl, p_xl, NN, aStride, Np, 726, 0, nkt);
    }
    compute_alpha_kernel<<<NN, 6 * 32>>>(p_xl, a_src3, a_dst3, 6, 121);
    gat_aggregate_kernel<<<dim3(NN, 6), 128>>>(p_xl, p_agg, 6, 121);
    head_mean_kernel<<<(NN * 121 + 255) / 256, 256>>>(p_agg, b3, out);
}

// round 9
// speedup vs baseline: 2.9969x; 1.4360x over previous
#include <cuda_runtime.h>
#include <cuda_bf16.h>
#include <cstdint>

#define NN 20000
#define MPAD 20096              // NN rounded up to 128
#define NE 320000
#define NT (NE + NN)

// ---------------- scratch (device globals; no allocations allowed) ----------
__device__ float g_xl[(size_t)NN * 1024];
__device__ float g_skip[(size_t)NN * 1024];
__device__ float g_agg[(size_t)NN * 1024];
__device__ uint32_t g_ah[(size_t)MPAD * 512];   // packed bf16-hi A plane
__device__ uint32_t g_al[(size_t)MPAD * 512];   // packed bf16-lo A plane
__device__ uint32_t g_bh[(size_t)512 * 2048];   // packed bf16-hi B plane
__device__ uint32_t g_bl[(size_t)512 * 2048];   // packed bf16-lo B plane
__device__ float g_asrc[NN * 6];
__device__ float g_adst[NN * 6];
__device__ float g_walpha[(size_t)NT * 6];      // unnormalized softmax weights (CSR order)
__device__ float g_adenom[NN * 6];
__device__ int   g_deg[NN];
__device__ int   g_row[NN + 1];
__device__ int   g_cursor[NN];
__device__ int   g_esrc[NT];
__device__ int   g_edst[NT];
__device__ int   g_csr_src[NT];
__device__ int   g_is64;

// ---------------- edge dtype detection --------------------------------------
__global__ void detect_dtype_kernel(const int* __restrict__ w) {
    if (threadIdx.x == 0) {
        int nz = 0;
        for (int i = 1; i < 2048; i += 2) nz += (w[i] != 0);
        g_is64 = (nz == 0) ? 1 : 0;
    }
}

// ---------------- graph construction ----------------------------------------
__global__ void zero_deg_kernel() {
    int i = blockIdx.x * blockDim.x + threadIdx.x;
    if (i < NN) g_deg[i] = 0;
}

__global__ void build_edges_kernel(const void* __restrict__ ei) {
    int t = blockIdx.x * blockDim.x + threadIdx.x;
    if (t >= NT) return;
    int s, d;
    if (t < NE) {
        if (g_is64) {
            const long long* p = (const long long*)ei;
            s = (int)p[t];
            d = (int)p[NE + t];
        } else {
            const int* p = (const int*)ei;
            s = p[t];
            d = p[NE + t];
        }
        s = min(max(s, 0), NN - 1);
        d = min(max(d, 0), NN - 1);
    } else {
        s = d = t - NE;  // self loop
    }
    g_esrc[t] = s;
    g_edst[t] = d;
    atomicAdd(&g_deg[d], 1);
}

__global__ void scan_kernel() {
    __shared__ int sh[1024];
    __shared__ int carry;
    int tid = threadIdx.x;
    if (tid == 0) { carry = 0; g_row[0] = 0; }
    __syncthreads();
    for (int base = 0; base < NN; base += 1024) {
        int i = base + tid;
        int v = (i < NN) ? g_deg[i] : 0;
        sh[tid] = v;
        __syncthreads();
        for (int off = 1; off < 1024; off <<= 1) {
            int t = (tid >= off) ? sh[tid - off] : 0;
            __syncthreads();
            sh[tid] += t;
            __syncthreads();
        }
        if (i < NN) {
            int incl = sh[tid];
            g_row[i + 1]  = carry + incl;
            g_cursor[i]   = carry + incl - v;
        }
        __syncthreads();
        if (tid == 0) carry += sh[1023];
        __syncthreads();
    }
}

__global__ void scatter_kernel() {
    int t = blockIdx.x * blockDim.x + threadIdx.x;
    if (t >= NT) return;
    int d = g_edst[t];
    int pos = atomicAdd(&g_cursor[d], 1);
    g_csr_src[pos] = g_esrc[t];
}

// ============================================================================
// hi/lo bf16 pre-conversion
// ============================================================================
__device__ __forceinline__ void packpair(float x0, float x1,
                                         uint32_t& hw, uint32_t& lw) {
    uint32_t b0 = __float_as_uint(x0), b1 = __float_as_uint(x1);
    uint32_t h0 = b0 & 0xFFFF0000u, h1 = b1 & 0xFFFF0000u;
    float l0 = x0 - __uint_as_float(h0);
    float l1 = x1 - __uint_as_float(h1);
    __nv_bfloat16 lb0 = __float2bfloat16(l0);
    __nv_bfloat16 lb1 = __float2bfloat16(l1);
    uint16_t u0 = *reinterpret_cast<uint16_t*>(&lb0);
    uint16_t u1 = *reinterpret_cast<uint16_t*>(&lb1);
    hw = (h0 >> 16) | h1;
    lw = (uint32_t)u0 | ((uint32_t)u1 << 16);
}

// A[M,K] fp32 -> packed word planes g_ah/g_al [MPAD][aStride]; zero pad.
__global__ void cvt_a_kernel(const float* __restrict__ A, int M, int K,
                             int aStride) {
    int t = blockIdx.x * blockDim.x + threadIdx.x;
    if (t >= MPAD * aStride) return;
    int row = t / aStride, kp = t - row * aStride;
    float x0 = 0.f, x1 = 0.f;
    if (row < M) {
        int k0 = kp * 2;
        const float* ap = &A[(size_t)row * K];
        if (k0 < K)     x0 = ap[k0];
        if (k0 + 1 < K) x1 = ap[k0 + 1];
    }
    uint32_t hw, lw;
    packpair(x0, x1, hw, lw);
    g_ah[t] = hw;
    g_al[t] = lw;
}

// Concat(B0[K,N0c], B1[K,N1c]) -> packed k-pair planes g_bh/g_bl [kpHalf][Np].
__global__ void cvt_w_kernel(const float* __restrict__ B0, int N0c,
                             const float* __restrict__ B1, int N1c,
                             int K, int Np, int kpHalf) {
    int t = blockIdx.x * blockDim.x + threadIdx.x;
    if (t >= kpHalf * Np) return;
    int kp = t / Np, n = t - kp * Np;
    int k0 = kp * 2;
    float x0 = 0.f, x1 = 0.f;
    if (n < N0c) {
        if (k0 < K)     x0 = B0[(size_t)k0 * N0c + n];
        if (k0 + 1 < K) x1 = B0[(size_t)(k0 + 1) * N0c + n];
    } else if (B1 != nullptr && n - N0c < N1c) {
        int nn = n - N0c;
        if (k0 < K)     x0 = B1[(size_t)k0 * N1c + nn];
        if (k0 + 1 < K) x1 = B1[(size_t)(k0 + 1) * N1c + nn];
    }
    uint32_t hw, lw;
    packpair(x0, x1, hw, lw);
    g_bh[t] = hw;
    g_bl[t] = lw;
}

// ============================================================================
// bf16x3 tensor-core GEMM, pre-converted operands, cp.async pipeline.
// CTA tile 128x128, BK=32. 8 warps 2x4 -> warp tile 64x32 (4x4 m16n8k16 x3).
// ============================================================================
#define AW  20
#define BW  136
#define A_P_STRIDE (128 * AW)
#define B_P_STRIDE (16 * BW)
#define BUF_WORDS  (2 * A_P_STRIDE + 2 * B_P_STRIDE)
#define GEMM_SMEM_BYTES (2 * BUF_WORDS * 4)

__device__ __forceinline__ void mma_bf16(float* c, const uint32_t* a,
                                         const uint32_t* b) {
    asm volatile(
        "mma.sync.aligned.m16n8k16.row.col.f32.bf16.bf16.f32 "
        "{%0,%1,%2,%3},{%4,%5,%6,%7},{%8,%9},{%0,%1,%2,%3};\n"
        : "+f"(c[0]), "+f"(c[1]), "+f"(c[2]), "+f"(c[3])
        : "r"(a[0]), "r"(a[1]), "r"(a[2]), "r"(a[3]), "r"(b[0]), "r"(b[1]));
}

__device__ __forceinline__ void cp16(uint32_t saddr, const void* g) {
    asm volatile("cp.async.ca.shared.global [%0], [%1], 16;\n"
                 :: "r"(saddr), "l"(g));
}

__global__ __launch_bounds__(256) void mma_gemm_async(
    const uint32_t* __restrict__ Ah, const uint32_t* __restrict__ Al,
    const uint32_t* __restrict__ Bh, const uint32_t* __restrict__ Bl,
    float* __restrict__ C0, float* __restrict__ C1,
    int M, int aStride, int Np, int N0, int ld0, int N1, int ld1, int nkt) {
    extern __shared__ uint32_t sm[];
    const int tid  = threadIdx.x;
    const int warp = tid >> 5, lane = tid & 31;
    const int group = lane >> 2, tg = lane & 3;
    const int wM = (warp >> 2) * 64;
    const int wN = (warp & 3) * 32;
    const int tileM = blockIdx.y * 128;
    const int tileN = blockIdx.x * 128;

    // A loader mapping: row, 8-word half per plane
    const int aRow = tid >> 1, aHalf = tid & 1;
    const size_t aGbase = (size_t)(tileM + aRow) * aStride + aHalf * 8;
    const uint32_t aSbase = aRow * AW + aHalf * 8;
    // B loader mapping: kp row, 8-word n chunk
    const int bKp = tid >> 4, bN0 = (tid & 15) * 8;
    const uint32_t bSbase = bKp * BW + bN0;

    auto issue = [&](int kt, int buf) {
        uint32_t* s = sm + buf * BUF_WORDS;
        {
            const uint32_t* gh = Ah + aGbase + kt * 16;
            const uint32_t* gl = Al + aGbase + kt * 16;
            uint32_t sh_ = (uint32_t)__cvta_generic_to_shared(s + aSbase);
            uint32_t sl_ = (uint32_t)__cvta_generic_to_shared(s + A_P_STRIDE + aSbase);
            cp16(sh_, gh); cp16(sh_ + 16, gh + 4);
            cp16(sl_, gl); cp16(sl_ + 16, gl + 4);
        }
        {
            const size_t go = (size_t)(kt * 16 + bKp) * Np + tileN + bN0;
            const uint32_t* gh = Bh + go;
            const uint32_t* gl = Bl + go;
            uint32_t* bs = s + 2 * A_P_STRIDE;
            uint32_t sh_ = (uint32_t)__cvta_generic_to_shared(bs + bSbase);
            uint32_t sl_ = (uint32_t)__cvta_generic_to_shared(bs + B_P_STRIDE + bSbase);
            cp16(sh_, gh); cp16(sh_ + 16, gh + 4);
            cp16(sl_, gl); cp16(sl_ + 16, gl + 4);
        }
    };

    float acc[4][4][4] = {};

    issue(0, 0);
    asm volatile("cp.async.commit_group;\n");

    for (int t = 0; t < nkt; t++) {
        const int cur = t & 1;
        const bool more = (t + 1 < nkt);
        if (more) {
            issue(t + 1, cur ^ 1);
            asm volatile("cp.async.commit_group;\n");
            asm volatile("cp.async.wait_group 1;\n");
        } else {
            asm volatile("cp.async.wait_group 0;\n");
        }
        __syncthreads();

        const uint32_t* As_ = sm + cur * BUF_WORDS;
        const uint32_t* Bs_ = sm + cur * BUF_WORDS + 2 * A_P_STRIDE;
#pragma unroll
        for (int ks = 0; ks < 2; ks++) {
            const int kb2 = ks * 8;
            uint32_t afr[4][2][4];
#pragma unroll
            for (int i = 0; i < 4; i++) {
                int row = wM + i * 16 + group;
#pragma unroll
                for (int p = 0; p < 2; p++) {
                    const uint32_t* Ap = As_ + p * A_P_STRIDE;
                    afr[i][p][0] = Ap[row * AW + kb2 + tg];
                    afr[i][p][1] = Ap[(row + 8) * AW + kb2 + tg];
                    afr[i][p][2] = Ap[row * AW + kb2 + 4 + tg];
                    afr[i][p][3] = Ap[(row + 8) * AW + kb2 + 4 + tg];
                }
            }
            uint32_t bfr[4][2][2];
#pragma unroll
            for (int j = 0; j < 4; j++) {
                int n = wN + j * 8 + group;
#pragma unroll
                for (int p = 0; p < 2; p++) {
                    const uint32_t* Bp = Bs_ + p * B_P_STRIDE;
                    bfr[j][p][0] = Bp[(kb2 + tg) * BW + n];
                    bfr[j][p][1] = Bp[(kb2 + 4 + tg) * BW + n];
                }
            }
#pragma unroll
            for (int i = 0; i < 4; i++)
#pragma unroll
                for (int j = 0; j < 4; j++) {
                    mma_bf16(acc[i][j], afr[i][0], bfr[j][0]);  // hi*hi
                    mma_bf16(acc[i][j], afr[i][0], bfr[j][1]);  // hi*lo
                    mma_bf16(acc[i][j], afr[i][1], bfr[j][0]);  // lo*hi
                }
        }
        __syncthreads();
    }

    // ---------------- epilogue: split store into C0 / C1 ----------------
    auto store = [&](int gm, int gn, float v) {
        if (gm >= M) return;
        if (gn < N0) {
            C0[(size_t)gm * ld0 + gn] = v;
        } else {
            int n2 = gn - N0;
            if (n2 < N1) C1[(size_t)gm * ld1 + n2] = v;
        }
    };
#pragma unroll
    for (int i = 0; i < 4; i++) {
        int row0 = tileM + wM + i * 16 + group;
#pragma unroll
        for (int j = 0; j < 4; j++) {
            int col0 = tileN + wN + j * 8 + tg * 2;
            store(row0,     col0,     acc[i][j][0]);
            store(row0,     col0 + 1, acc[i][j][1]);
            store(row0 + 8, col0,     acc[i][j][2]);
            store(row0 + 8, col0 + 1, acc[i][j][3]);
        }
    }
}

// ---------------- per-node attention logits ---------------------------------
// xl row layout: node n at xl + n*LD, channel (h,c) at h*C + c
__global__ void compute_alpha_kernel(const float* __restrict__ xl,
                                     const float* __restrict__ a_src,
                                     const float* __restrict__ a_dst,
                                     int H, int C, int LD) {
    int n = blockIdx.x;
    int h = threadIdx.x >> 5;
    int lane = threadIdx.x & 31;
    const float* xr = xl + (size_t)n * LD + h * C;
    float ss = 0.f, sd = 0.f;
    for (int c = lane; c < C; c += 32) {
        float v = xr[c];
        ss += v * a_src[h * C + c];
        sd += v * a_dst[h * C + c];
    }
#pragma unroll
    for (int off = 16; off > 0; off >>= 1) {
        ss += __shfl_down_sync(0xffffffffu, ss, off);
        sd += __shfl_down_sync(0xffffffffu, sd, off);
    }
    if (lane == 0) {
        g_asrc[n * H + h] = ss;
        g_adst[n * H + h] = sd;
    }
}

// ---------------- edge softmax: weights + denominator (CSR order) ------------
// one warp per (dst, head)
__global__ void edge_softmax_kernel(int H) {
    int d = blockIdx.x;
    int h = threadIdx.x >> 5;
    int lane = threadIdx.x & 31;
    int r0 = g_row[d], r1 = g_row[d + 1];
    float adv = g_adst[d * H + h];

    float mx = -1e30f;
    for (int j = r0 + lane; j < r1; j += 32)
        mx = fmaxf(mx, g_asrc[g_csr_src[j] * H + h]);
#pragma unroll
    for (int off = 16; off > 0; off >>= 1)
        mx = fmaxf(mx, __shfl_xor_sync(0xffffffffu, mx, off));
    float m = mx + adv;
    m = (m > 0.f) ? m : 0.2f * m;  // leaky relu commutes with max (monotonic)

    float sum = 0.f;
    for (int j = r0 + lane; j < r1; j += 32) {
        float e = g_asrc[g_csr_src[j] * H + h] + adv;
        e = (e > 0.f) ? e : 0.2f * e;
        float w = __expf(e - m);
        g_walpha[(size_t)j * H + h] = w;
        sum += w;
    }
#pragma unroll
    for (int off = 16; off > 0; off >>= 1)
        sum += __shfl_xor_sync(0xffffffffu, sum, off);
    if (lane == 0) g_adenom[d * H + h] = sum;
}

// ---------------- gather: one block per dst, all heads, float4 ---------------
template <bool ALIGNED>
__global__ void gat_gather_kernel(const float* __restrict__ xl,
                                  float* __restrict__ out,
                                  int H, int C, int LD, int HC) {
    int d = blockIdx.x;
    int tid = threadIdx.x;
    int f = tid * 4;
    int r0 = g_row[d], r1 = g_row[d + 1];

    int h0, h1, h2, h3;
    bool active;
    if (ALIGNED) {
        h0 = h1 = h2 = h3 = f / C;
        active = true;
    } else {
        active = (f < HC);
        h0 = min(f / C, H - 1);
        h1 = min((f + 1) / C, H - 1);
        h2 = min((f + 2) / C, H - 1);
        h3 = min((f + 3) / C, H - 1);
    }

    float4 acc = make_float4(0.f, 0.f, 0.f, 0.f);
    int j = r0;
    if (active) {
        for (; j + 1 < r1; j += 2) {
            int s0 = g_csr_src[j], s1 = g_csr_src[j + 1];
            const float* wp0 = &g_walpha[(size_t)j * H];
            const float* wp1 = &g_walpha[(size_t)(j + 1) * H];
            float4 v0 = *(reinterpret_cast<const float4*>(xl + (size_t)s0 * LD) + tid);
            float4 v1 = *(reinterpret_cast<const float4*>(xl + (size_t)s1 * LD) + tid);
            if (ALIGNED) {
                float w0 = wp0[h0], w1 = wp1[h0];
                acc.x += w0 * v0.x + w1 * v1.x;
                acc.y += w0 * v0.y + w1 * v1.y;
                acc.z += w0 * v0.z + w1 * v1.z;
                acc.w += w0 * v0.w + w1 * v1.w;
            } else {
                acc.x += wp0[h0] * v0.x + wp1[h0] * v1.x;
                acc.y += wp0[h1] * v0.y + wp1[h1] * v1.y;
                acc.z += wp0[h2] * v0.z + wp1[h2] * v1.z;
                acc.w += wp0[h3] * v0.w + wp1[h3] * v1.w;
            }
        }
        if (j < r1) {
            int s0 = g_csr_src[j];
            const float* wp0 = &g_walpha[(size_t)j * H];
            float4 v0 = *(reinterpret_cast<const float4*>(xl + (size_t)s0 * LD) + tid);
            acc.x += wp0[h0] * v0.x;
            acc.y += wp0[h1] * v0.y;
            acc.z += wp0[h2] * v0.z;
            acc.w += wp0[h3] * v0.w;
        }
    }

    if (!active) return;
    const float* dn = &g_adenom[d * H];
    float* o = out + (size_t)d * LD;
    if (ALIGNED) {
        float inv = 1.f / (dn[h0] + 1e-16f);
        float4 r = make_float4(acc.x * inv, acc.y * inv, acc.z * inv, acc.w * inv);
        *(reinterpret_cast<float4*>(o + f)) = r;
    } else {
        if (f < HC)     o[f]     = acc.x / (dn[h0] + 1e-16f);
        if (f + 1 < HC) o[f + 1] = acc.y / (dn[h1] + 1e-16f);
        if (f + 2 < HC) o[f + 2] = acc.z / (dn[h2] + 1e-16f);
        if (f + 3 < HC) o[f + 3] = acc.w / (dn[h3] + 1e-16f);
    }
}

// ---------------- fused add-skip + layernorm + elu -> packed bf16 planes -----
// width fixed 1024; writes g_ah/g_al rows [row][512 words] for the next GEMM.
__global__ __launch_bounds__(256) void ln_elu_pack_kernel(
    const float* __restrict__ agg, const float* __restrict__ b,
    const float* __restrict__ skip, const float* __restrict__ skipb,
    const float* __restrict__ g, const float* __restrict__ beta) {
    int row = blockIdx.x;
    int tid = threadIdx.x;
    const size_t base = (size_t)row * 1024;
    int f = tid * 4;
    float4 a4 = *(const float4*)(agg + base + f);
    float4 s4 = *(const float4*)(skip + base + f);
    float4 b4 = *(const float4*)(b + f);
    float4 sb4 = *(const float4*)(skipb + f);
    float pre[4] = {a4.x + s4.x + b4.x + sb4.x, a4.y + s4.y + b4.y + sb4.y,
                    a4.z + s4.z + b4.z + sb4.z, a4.w + s4.w + b4.w + sb4.w};
    float sum = pre[0] + pre[1] + pre[2] + pre[3];
    __shared__ float red[256];
    red[tid] = sum;
    __syncthreads();
    for (int s = 128; s > 0; s >>= 1) {
        if (tid < s) red[tid] += red[tid + s];
        __syncthreads();
    }
    float mu = red[0] * (1.f / 1024.f);
    __syncthreads();
    float sq = 0.f;
#pragma unroll
    for (int k = 0; k < 4; k++) {
        float dlt = pre[k] - mu;
        sq += dlt * dlt;
    }
    red[tid] = sq;
    __syncthreads();
    for (int s = 128; s > 0; s >>= 1) {
        if (tid < s) red[tid] += red[tid + s];
        __syncthreads();
    }
    float rstd = rsqrtf(red[0] * (1.f / 1024.f) + 1e-5f);
    float4 g4 = *(const float4*)(g + f);
    float4 be4 = *(const float4*)(beta + f);
    float y[4];
    y[0] = (pre[0] - mu) * rstd * g4.x + be4.x;
    y[1] = (pre[1] - mu) * rstd * g4.y + be4.y;
    y[2] = (pre[2] - mu) * rstd * g4.z + be4.z;
    y[3] = (pre[3] - mu) * rstd * g4.w + be4.w;
#pragma unroll
    for (int k = 0; k < 4; k++) y[k] = (y[k] > 0.f) ? y[k] : expm1f(y[k]);
    uint32_t hw0, lw0, hw1, lw1;
    packpair(y[0], y[1], hw0, lw0);
    packpair(y[2], y[3], hw1, lw1);
    size_t w = (size_t)row * 512 + 2 * tid;
    g_ah[w] = hw0; g_ah[w + 1] = hw1;
    g_al[w] = lw0; g_al[w + 1] = lw1;
}

// ---------------- final head-mean + bias -------------------------------------
__global__ void head_mean_kernel(const float* __restrict__ agg,
                                 const float* __restrict__ b3,
                                 float* __restrict__ out) {
    int idx = blockIdx.x * blockDim.x + threadIdx.x;
    if (idx >= NN * 121) return;
    int n = idx / 121, c = idx % 121;
    float s = 0.f;
#pragma unroll
    for (int h = 0; h < 6; h++) s += agg[(size_t)n * 728 + h * 121 + c];
    out[idx] = s * (1.f / 6.f) + b3[c];
}

// ---------------- host orchestration -----------------------------------------
extern "C" void kernel_launch(void* const* d_in, const int* in_sizes, int n_in,
                              void* d_out, int out_size) {
    const float* x      = (const float*)d_in[0];
    const void*  ei     = d_in[1];
    const float* W1     = (const float*)d_in[2];
    const float* a_src1 = (const float*)d_in[3];
    const float* a_dst1 = (const float*)d_in[4];
    const float* b1     = (const float*)d_in[5];
    const float* W2     = (const float*)d_in[6];
    const float* a_src2 = (const float*)d_in[7];
    const float* a_dst2 = (const float*)d_in[8];
    const float* b2     = (const float*)d_in[9];
    const float* W3     = (const float*)d_in[10];
    const float* a_src3 = (const float*)d_in[11];
    const float* a_dst3 = (const float*)d_in[12];
    const float* b3     = (const float*)d_in[13];
    const float* skipW1 = (const float*)d_in[14];
    const float* skipb1 = (const float*)d_in[15];
    const float* skipW2 = (const float*)d_in[16];
    const float* skipb2 = (const float*)d_in[17];
    const float* g1     = (const float*)d_in[18];
    const float* beta1  = (const float*)d_in[19];
    const float* g2     = (const float*)d_in[20];
    const float* beta2  = (const float*)d_in[21];
    float* out = (float*)d_out;

    float *p_xl, *p_skip, *p_agg;
    uint32_t *p_ah, *p_al, *p_bh, *p_bl;
    cudaGetSymbolAddress((void**)&p_xl, g_xl);
    cudaGetSymbolAddress((void**)&p_skip, g_skip);
    cudaGetSymbolAddress((void**)&p_agg, g_agg);
    cudaGetSymbolAddress((void**)&p_ah, g_ah);
    cudaGetSymbolAddress((void**)&p_al, g_al);
    cudaGetSymbolAddress((void**)&p_bh, g_bh);
    cudaGetSymbolAddress((void**)&p_bl, g_bl);

    cudaFuncSetAttribute(mma_gemm_async,
                         cudaFuncAttributeMaxDynamicSharedMemorySize,
                         GEMM_SMEM_BYTES);

    // ---- CSR build (edges shared by all 3 layers) ----
    detect_dtype_kernel<<<1, 32>>>((const int*)ei);
    zero_deg_kernel<<<(NN + 255) / 256, 256>>>();
    build_edges_kernel<<<(NT + 255) / 256, 256>>>(ei);
    scan_kernel<<<1, 1024>>>();
    scatter_kernel<<<(NT + 255) / 256, 256>>>();

    const int gridM = MPAD / 128;   // 157

    // ---- Layer 1: GATConv(50 -> 256, H=4, concat) + skip; K=50 Kpad=64 ----
    {
        const int K = 50, aStride = 32, nkt = 2, Np = 2048;
        cvt_w_kernel<<<((Np * aStride) + 255) / 256, 256>>>(
            W1, 1024, skipW1, 1024, K, Np, aStride);
        cvt_a_kernel<<<((MPAD * aStride) + 255) / 256, 256>>>(x, NN, K, aStride);
        mma_gemm_async<<<dim3(Np / 128, gridM), 256, GEMM_SMEM_BYTES>>>(
            p_ah, p_al, p_bh, p_bl, p_xl, p_skip, NN, aStride, Np,
            1024, 1024, 1024, 1024, nkt);
    }
    compute_alpha_kernel<<<NN, 4 * 32>>>(p_xl, a_src1, a_dst1, 4, 256, 1024);
    edge_softmax_kernel<<<NN, 4 * 32>>>(4);
    gat_gather_kernel<true><<<NN, 256>>>(p_xl, p_agg, 4, 256, 1024, 1024);
    ln_elu_pack_kernel<<<NN, 256>>>(p_agg, b1, p_skip, skipb1, g1, beta1);

    // ---- Layer 2: GATConv(1024 -> 256, H=4, concat) + skip ----
    {
        const int aStride = 512, nkt = 32, Np = 2048;
        cvt_w_kernel<<<((Np * aStride) + 255) / 256, 256>>>(
            W2, 1024, skipW2, 1024, 1024, Np, aStride);
        mma_gemm_async<<<dim3(Np / 128, gridM), 256, GEMM_SMEM_BYTES>>>(
            p_ah, p_al, p_bh, p_bl, p_xl, p_skip, NN, aStride, Np,
            1024, 1024, 1024, 1024, nkt);
    }
    compute_alpha_kernel<<<NN, 4 * 32>>>(p_xl, a_src2, a_dst2, 4, 256, 1024);
    edge_softmax_kernel<<<NN, 4 * 32>>>(4);
    gat_gather_kernel<true><<<NN, 256>>>(p_xl, p_agg, 4, 256, 1024, 1024);
    ln_elu_pack_kernel<<<NN, 256>>>(p_agg, b2, p_skip, skipb2, g2, beta2);

    // ---- Layer 3: GATConv(1024 -> 121, H=6, mean); N=726, row stride 728 ----
    {
        const int aStride = 512, nkt = 32, Np = 768;
        cvt_w_kernel<<<((Np * aStride) + 255) / 256, 256>>>(
            W3, 726, (const float*)nullptr, 0, 1024, Np, aStride);
        mma_gemm_async<<<dim3(Np / 128, gridM), 256, GEMM_SMEM_BYTES>>>(
            p_ah, p_al, p_bh, p_bl, p_xl, p_xl, NN, aStride, Np,
            726, 728, 0, 728, nkt);
    }
    compute_alpha_kernel<<<NN, 6 * 32>>>(p_xl, a_src3, a_dst3, 6, 121, 728);
    edge_softmax_kernel<<<NN, 6 * 32>>>(6);
    gat_gather_kernel<false><<<NN, 192>>>(p_xl, p_agg, 6, 121, 728, 726);
    head_mean_kernel<<<(NN * 121 + 255) / 256, 256>>>(p_agg, b3, out);
}

// round 11
// speedup vs baseline: 3.2716x; 1.0917x over previous
#include <cuda_runtime.h>
#include <cuda_bf16.h>
#include <cstdint>

#define NN 20000
#define MPAD 20096              // NN rounded up to 128
#define NE 320000
#define NT (NE + NN)

// ---------------- scratch (device globals; no allocations allowed) ----------
__device__ float g_xl[(size_t)NN * 1024];
__device__ float g_skip[(size_t)NN * 1024];
__device__ float g_agg[(size_t)NN * 1024];
__device__ uint32_t g_ah[(size_t)MPAD * 512];   // packed bf16-hi A plane
__device__ uint32_t g_al[(size_t)MPAD * 512];   // packed bf16-lo A plane
__device__ uint32_t g_bh[(size_t)512 * 2048];   // packed bf16-hi B plane
__device__ uint32_t g_bl[(size_t)512 * 2048];   // packed bf16-lo B plane
__device__ float g_asrc[NN * 6];
__device__ float g_adst[NN * 6];
__device__ float g_walpha[(size_t)NT * 6];      // unnormalized softmax weights (CSR order)
__device__ float g_adenom[NN * 6];
__device__ int   g_deg[NN];
__device__ int   g_row[NN + 1];
__device__ int   g_cursor[NN];
__device__ int   g_esrc[NT];
__device__ int   g_edst[NT];
__device__ int   g_csr_src[NT];
__device__ int   g_is64;

// ---------------- edge dtype detection --------------------------------------
__global__ void detect_dtype_kernel(const int* __restrict__ w) {
    if (threadIdx.x == 0) {
        int nz = 0;
        for (int i = 1; i < 2048; i += 2) nz += (w[i] != 0);
        g_is64 = (nz == 0) ? 1 : 0;
    }
}

// ---------------- graph construction ----------------------------------------
__global__ void zero_deg_kernel() {
    int i = blockIdx.x * blockDim.x + threadIdx.x;
    if (i < NN) g_deg[i] = 0;
}

__global__ void build_edges_kernel(const void* __restrict__ ei) {
    int t = blockIdx.x * blockDim.x + threadIdx.x;
    if (t >= NT) return;
    int s, d;
    if (t < NE) {
        if (g_is64) {
            const long long* p = (const long long*)ei;
            s = (int)p[t];
            d = (int)p[NE + t];
        } else {
            const int* p = (const int*)ei;
            s = p[t];
            d = p[NE + t];
        }
        s = min(max(s, 0), NN - 1);
        d = min(max(d, 0), NN - 1);
    } else {
        s = d = t - NE;  // self loop
    }
    g_esrc[t] = s;
    g_edst[t] = d;
    atomicAdd(&g_deg[d], 1);
}

__global__ void scan_kernel() {
    __shared__ int sh[1024];
    __shared__ int carry;
    int tid = threadIdx.x;
    if (tid == 0) { carry = 0; g_row[0] = 0; }
    __syncthreads();
    for (int base = 0; base < NN; base += 1024) {
        int i = base + tid;
        int v = (i < NN) ? g_deg[i] : 0;
        sh[tid] = v;
        __syncthreads();
        for (int off = 1; off < 1024; off <<= 1) {
            int t = (tid >= off) ? sh[tid - off] : 0;
            __syncthreads();
            sh[tid] += t;
            __syncthreads();
        }
        if (i < NN) {
            int incl = sh[tid];
            g_row[i + 1]  = carry + incl;
            g_cursor[i]   = carry + incl - v;
        }
        __syncthreads();
        if (tid == 0) carry += sh[1023];
        __syncthreads();
    }
}

__global__ void scatter_kernel() {
    int t = blockIdx.x * blockDim.x + threadIdx.x;
    if (t >= NT) return;
    int d = g_edst[t];
    int pos = atomicAdd(&g_cursor[d], 1);
    g_csr_src[pos] = g_esrc[t];
}

// ============================================================================
// hi/lo bf16 pre-conversion
// ============================================================================
__device__ __forceinline__ void packpair(float x0, float x1,
                                         uint32_t& hw, uint32_t& lw) {
    uint32_t b0 = __float_as_uint(x0), b1 = __float_as_uint(x1);
    uint32_t h0 = b0 & 0xFFFF0000u, h1 = b1 & 0xFFFF0000u;
    float l0 = x0 - __uint_as_float(h0);
    float l1 = x1 - __uint_as_float(h1);
    __nv_bfloat16 lb0 = __float2bfloat16(l0);
    __nv_bfloat16 lb1 = __float2bfloat16(l1);
    uint16_t u0 = *reinterpret_cast<uint16_t*>(&lb0);
    uint16_t u1 = *reinterpret_cast<uint16_t*>(&lb1);
    hw = (h0 >> 16) | h1;
    lw = (uint32_t)u0 | ((uint32_t)u1 << 16);
}

// A[M,K] fp32 -> packed word planes g_ah/g_al [MPAD][aStride]; zero pad.
__global__ void cvt_a_kernel(const float* __restrict__ A, int M, int K,
                             int aStride) {
    int t = blockIdx.x * blockDim.x + threadIdx.x;
    if (t >= MPAD * aStride) return;
    int row = t / aStride, kp = t - row * aStride;
    float x0 = 0.f, x1 = 0.f;
    if (row < M) {
        int k0 = kp * 2;
        const float* ap = &A[(size_t)row * K];
        if (k0 < K)     x0 = ap[k0];
        if (k0 + 1 < K) x1 = ap[k0 + 1];
    }
    uint32_t hw, lw;
    packpair(x0, x1, hw, lw);
    g_ah[t] = hw;
    g_al[t] = lw;
}

// Concat(B0[K,N0c], B1[K,N1c]) -> packed k-pair planes g_bh/g_bl [kpHalf][Np].
__global__ void cvt_w_kernel(const float* __restrict__ B0, int N0c,
                             const float* __restrict__ B1, int N1c,
                             int K, int Np, int kpHalf) {
    int t = blockIdx.x * blockDim.x + threadIdx.x;
    if (t >= kpHalf * Np) return;
    int kp = t / Np, n = t - kp * Np;
    int k0 = kp * 2;
    float x0 = 0.f, x1 = 0.f;
    if (n < N0c) {
        if (k0 < K)     x0 = B0[(size_t)k0 * N0c + n];
        if (k0 + 1 < K) x1 = B0[(size_t)(k0 + 1) * N0c + n];
    } else if (B1 != nullptr && n - N0c < N1c) {
        int nn = n - N0c;
        if (k0 < K)     x0 = B1[(size_t)k0 * N1c + nn];
        if (k0 + 1 < K) x1 = B1[(size_t)(k0 + 1) * N1c + nn];
    }
    uint32_t hw, lw;
    packpair(x0, x1, hw, lw);
    g_bh[t] = hw;
    g_bl[t] = lw;
}

// ============================================================================
// bf16x3 tensor-core GEMM, pre-converted operands, cp.async pipeline.
// CTA tile 128x128, BK=32. 8 warps 2x4 -> warp tile 64x32 (4x4 m16n8k16 x3).
// ============================================================================
#define AW  20
#define BW  136
#define A_P_STRIDE (128 * AW)
#define B_P_STRIDE (16 * BW)
#define BUF_WORDS  (2 * A_P_STRIDE + 2 * B_P_STRIDE)
#define GEMM_SMEM_BYTES (2 * BUF_WORDS * 4)

__device__ __forceinline__ void mma_bf16(float* c, const uint32_t* a,
                                         const uint32_t* b) {
    asm volatile(
        "mma.sync.aligned.m16n8k16.row.col.f32.bf16.bf16.f32 "
        "{%0,%1,%2,%3},{%4,%5,%6,%7},{%8,%9},{%0,%1,%2,%3};\n"
        : "+f"(c[0]), "+f"(c[1]), "+f"(c[2]), "+f"(c[3])
        : "r"(a[0]), "r"(a[1]), "r"(a[2]), "r"(a[3]), "r"(b[0]), "r"(b[1]));
}

__device__ __forceinline__ void cp16(uint32_t saddr, const void* g) {
    asm volatile("cp.async.cg.shared.global [%0], [%1], 16;\n"
                 :: "r"(saddr), "l"(g));
}

__global__ __launch_bounds__(256, 2) void mma_gemm_async(
    const uint32_t* __restrict__ Ah, const uint32_t* __restrict__ Al,
    const uint32_t* __restrict__ Bh, const uint32_t* __restrict__ Bl,
    float* __restrict__ C0, float* __restrict__ C1,
    int M, int aStride, int Np, int N0, int ld0, int N1, int ld1, int nkt) {
    extern __shared__ uint32_t sm[];
    const int tid  = threadIdx.x;
    const int warp = tid >> 5, lane = tid & 31;
    const int group = lane >> 2, tg = lane & 3;
    const int wM = (warp >> 2) * 64;
    const int wN = (warp & 3) * 32;
    const int tileM = blockIdx.y * 128;
    const int tileN = blockIdx.x * 128;

    // A loader mapping: row, 8-word half per plane
    const int aRow = tid >> 1, aHalf = tid & 1;
    const size_t aGbase = (size_t)(tileM + aRow) * aStride + aHalf * 8;
    const uint32_t aSbase = aRow * AW + aHalf * 8;
    // B loader mapping: kp row, 8-word n chunk
    const int bKp = tid >> 4, bN0 = (tid & 15) * 8;
    const uint32_t bSbase = bKp * BW + bN0;

    auto issue = [&](int kt, int buf) {
        uint32_t* s = sm + buf * BUF_WORDS;
        {
            const uint32_t* gh = Ah + aGbase + kt * 16;
            const uint32_t* gl = Al + aGbase + kt * 16;
            uint32_t sh_ = (uint32_t)__cvta_generic_to_shared(s + aSbase);
            uint32_t sl_ = (uint32_t)__cvta_generic_to_shared(s + A_P_STRIDE + aSbase);
            cp16(sh_, gh); cp16(sh_ + 16, gh + 4);
            cp16(sl_, gl); cp16(sl_ + 16, gl + 4);
        }
        {
            const size_t go = (size_t)(kt * 16 + bKp) * Np + tileN + bN0;
            const uint32_t* gh = Bh + go;
            const uint32_t* gl = Bl + go;
            uint32_t* bs = s + 2 * A_P_STRIDE;
            uint32_t sh_ = (uint32_t)__cvta_generic_to_shared(bs + bSbase);
            uint32_t sl_ = (uint32_t)__cvta_generic_to_shared(bs + B_P_STRIDE + bSbase);
            cp16(sh_, gh); cp16(sh_ + 16, gh + 4);
            cp16(sl_, gl); cp16(sl_ + 16, gl + 4);
        }
    };

    float acc[4][4][4] = {};

    issue(0, 0);
    asm volatile("cp.async.commit_group;\n");

    for (int t = 0; t < nkt; t++) {
        const int cur = t & 1;
        const bool more = (t + 1 < nkt);
        if (more) {
            issue(t + 1, cur ^ 1);
            asm volatile("cp.async.commit_group;\n");
            asm volatile("cp.async.wait_group 1;\n");
        } else {
            asm volatile("cp.async.wait_group 0;\n");
        }
        __syncthreads();

        const uint32_t* As_ = sm + cur * BUF_WORDS;
        const uint32_t* Bs_ = sm + cur * BUF_WORDS + 2 * A_P_STRIDE;
#pragma unroll
        for (int ks = 0; ks < 2; ks++) {
            const int kb2 = ks * 8;
            uint32_t afr[4][2][4];
#pragma unroll
            for (int i = 0; i < 4; i++) {
                int row = wM + i * 16 + group;
#pragma unroll
                for (int p = 0; p < 2; p++) {
                    const uint32_t* Ap = As_ + p * A_P_STRIDE;
                    afr[i][p][0] = Ap[row * AW + kb2 + tg];
                    afr[i][p][1] = Ap[(row + 8) * AW + kb2 + tg];
                    afr[i][p][2] = Ap[row * AW + kb2 + 4 + tg];
                    afr[i][p][3] = Ap[(row + 8) * AW + kb2 + 4 + tg];
                }
            }
            uint32_t bfr[4][2][2];
#pragma unroll
            for (int j = 0; j < 4; j++) {
                int n = wN + j * 8 + group;
#pragma unroll
                for (int p = 0; p < 2; p++) {
                    const uint32_t* Bp = Bs_ + p * B_P_STRIDE;
                    bfr[j][p][0] = Bp[(kb2 + tg) * BW + n];
                    bfr[j][p][1] = Bp[(kb2 + 4 + tg) * BW + n];
                }
            }
            // three independent sweeps: consecutive MMAs hit different
            // accumulators (dep distance 16) instead of same-acc chains
#pragma unroll
            for (int i = 0; i < 4; i++)
#pragma unroll
                for (int j = 0; j < 4; j++)
                    mma_bf16(acc[i][j], afr[i][0], bfr[j][0]);  // hi*hi
#pragma unroll
            for (int i = 0; i < 4; i++)
#pragma unroll
                for (int j = 0; j < 4; j++)
                    mma_bf16(acc[i][j], afr[i][0], bfr[j][1]);  // hi*lo
#pragma unroll
            for (int i = 0; i < 4; i++)
#pragma unroll
                for (int j = 0; j < 4; j++)
                    mma_bf16(acc[i][j], afr[i][1], bfr[j][0]);  // lo*hi
        }
        __syncthreads();
    }

    // ---------------- epilogue: split store into C0 / C1 ----------------
    auto store = [&](int gm, int gn, float v) {
        if (gm >= M) return;
        if (gn < N0) {
            C0[(size_t)gm * ld0 + gn] = v;
        } else {
            int n2 = gn - N0;
            if (n2 < N1) C1[(size_t)gm * ld1 + n2] = v;
        }
    };
#pragma unroll
    for (int i = 0; i < 4; i++) {
        int row0 = tileM + wM + i * 16 + group;
#pragma unroll
        for (int j = 0; j < 4; j++) {
            int col0 = tileN + wN + j * 8 + tg * 2;
            store(row0,     col0,     acc[i][j][0]);
            store(row0,     col0 + 1, acc[i][j][1]);
            store(row0 + 8, col0,     acc[i][j][2]);
            store(row0 + 8, col0 + 1, acc[i][j][3]);
        }
    }
}

// ---------------- per-node attention logits ---------------------------------
__global__ void compute_alpha_kernel(const float* __restrict__ xl,
                                     const float* __restrict__ a_src,
                                     const float* __restrict__ a_dst,
                                     int H, int C, int LD) {
    int n = blockIdx.x;
    int h = threadIdx.x >> 5;
    int lane = threadIdx.x & 31;
    const float* xr = xl + (size_t)n * LD + h * C;
    float ss = 0.f, sd = 0.f;
    for (int c = lane; c < C; c += 32) {
        float v = xr[c];
        ss += v * a_src[h * C + c];
        sd += v * a_dst[h * C + c];
    }
#pragma unroll
    for (int off = 16; off > 0; off >>= 1) {
        ss += __shfl_down_sync(0xffffffffu, ss, off);
        sd += __shfl_down_sync(0xffffffffu, sd, off);
    }
    if (lane == 0) {
        g_asrc[n * H + h] = ss;
        g_adst[n * H + h] = sd;
    }
}

// ---------------- edge softmax: weights + denominator (CSR order) ------------
__global__ void edge_softmax_kernel(int H) {
    int d = blockIdx.x;
    int h = threadIdx.x >> 5;
    int lane = threadIdx.x & 31;
    int r0 = g_row[d], r1 = g_row[d + 1];
    float adv = g_adst[d * H + h];

    float mx = -1e30f;
    for (int j = r0 + lane; j < r1; j += 32)
        mx = fmaxf(mx, g_asrc[g_csr_src[j] * H + h]);
#pragma unroll
    for (int off = 16; off > 0; off >>= 1)
        mx = fmaxf(mx, __shfl_xor_sync(0xffffffffu, mx, off));
    float m = mx + adv;
    m = (m > 0.f) ? m : 0.2f * m;  // leaky relu commutes with max (monotonic)

    float sum = 0.f;
    for (int j = r0 + lane; j < r1; j += 32) {
        float e = g_asrc[g_csr_src[j] * H + h] + adv;
        e = (e > 0.f) ? e : 0.2f * e;
        float w = __expf(e - m);
        g_walpha[(size_t)j * H + h] = w;
        sum += w;
    }
#pragma unroll
    for (int off = 16; off > 0; off >>= 1)
        sum += __shfl_xor_sync(0xffffffffu, sum, off);
    if (lane == 0) g_adenom[d * H + h] = sum;
}

// ---------------- gather: one block per dst, all heads, float4 ---------------
template <bool ALIGNED>
__global__ void gat_gather_kernel(const float* __restrict__ xl,
                                  float* __restrict__ out,
                                  int H, int C, int LD, int HC) {
    int d = blockIdx.x;
    int tid = threadIdx.x;
    int f = tid * 4;
    int r0 = g_row[d], r1 = g_row[d + 1];

    int h0, h1, h2, h3;
    bool active;
    if (ALIGNED) {
        h0 = h1 = h2 = h3 = f / C;
        active = true;
    } else {
        active = (f < HC);
        h0 = min(f / C, H - 1);
        h1 = min((f + 1) / C, H - 1);
        h2 = min((f + 2) / C, H - 1);
        h3 = min((f + 3) / C, H - 1);
    }

    float4 acc = make_float4(0.f, 0.f, 0.f, 0.f);
    int j = r0;
    if (active) {
        for (; j + 1 < r1; j += 2) {
            int s0 = g_csr_src[j], s1 = g_csr_src[j + 1];
            const float* wp0 = &g_walpha[(size_t)j * H];
            const float* wp1 = &g_walpha[(size_t)(j + 1) * H];
            float4 v0 = *(reinterpret_cast<const float4*>(xl + (size_t)s0 * LD) + tid);
            float4 v1 = *(reinterpret_cast<const float4*>(xl + (size_t)s1 * LD) + tid);
            if (ALIGNED) {
                float w0 = wp0[h0], w1 = wp1[h0];
                acc.x += w0 * v0.x + w1 * v1.x;
                acc.y += w0 * v0.y + w1 * v1.y;
                acc.z += w0 * v0.z + w1 * v1.z;
                acc.w += w0 * v0.w + w1 * v1.w;
            } else {
                acc.x += wp0[h0] * v0.x + wp1[h0] * v1.x;
                acc.y += wp0[h1] * v0.y + wp1[h1] * v1.y;
                acc.z += wp0[h2] * v0.z + wp1[h2] * v1.z;
                acc.w += wp0[h3] * v0.w + wp1[h3] * v1.w;
            }
        }
        if (j < r1) {
            int s0 = g_csr_src[j];
            const float* wp0 = &g_walpha[(size_t)j * H];
            float4 v0 = *(reinterpret_cast<const float4*>(xl + (size_t)s0 * LD) + tid);
            acc.x += wp0[h0] * v0.x;
            acc.y += wp0[h1] * v0.y;
            acc.z += wp0[h2] * v0.z;
            acc.w += wp0[h3] * v0.w;
        }
    }

    if (!active) return;
    const float* dn = &g_adenom[d * H];
    float* o = out + (size_t)d * LD;
    if (ALIGNED) {
        float inv = 1.f / (dn[h0] + 1e-16f);
        float4 r = make_float4(acc.x * inv, acc.y * inv, acc.z * inv, acc.w * inv);
        *(reinterpret_cast<float4*>(o + f)) = r;
    } else {
        if (f < HC)     o[f]     = acc.x / (dn[h0] + 1e-16f);
        if (f + 1 < HC) o[f + 1] = acc.y / (dn[h1] + 1e-16f);
        if (f + 2 < HC) o[f + 2] = acc.z / (dn[h2] + 1e-16f);
        if (f + 3 < HC) o[f + 3] = acc.w / (dn[h3] + 1e-16f);
    }
}

// ---------------- fused add-skip + layernorm + elu -> packed bf16 planes -----
__global__ __launch_bounds__(256) void ln_elu_pack_kernel(
    const float* __restrict__ agg, const float* __restrict__ b,
    const float* __restrict__ skip, const float* __restrict__ skipb,
    const float* __restrict__ g, const float* __restrict__ beta) {
    int row = blockIdx.x;
    int tid = threadIdx.x;
    const size_t base = (size_t)row * 1024;
    int f = tid * 4;
    float4 a4 = *(const float4*)(agg + base + f);
    float4 s4 = *(const float4*)(skip + base + f);
    float4 b4 = *(const float4*)(b + f);
    float4 sb4 = *(const float4*)(skipb + f);
    float pre[4] = {a4.x + s4.x + b4.x + sb4.x, a4.y + s4.y + b4.y + sb4.y,
                    a4.z + s4.z + b4.z + sb4.z, a4.w + s4.w + b4.w + sb4.w};
    float sum = pre[0] + pre[1] + pre[2] + pre[3];
    __shared__ float red[256];
    red[tid] = sum;
    __syncthreads();
    for (int s = 128; s > 0; s >>= 1) {
        if (tid < s) red[tid] += red[tid + s];
        __syncthreads();
    }
    float mu = red[0] * (1.f / 1024.f);
    __syncthreads();
    float sq = 0.f;
#pragma unroll
    for (int k = 0; k < 4; k++) {
        float dlt = pre[k] - mu;
        sq += dlt * dlt;
    }
    red[tid] = sq;
    __syncthreads();
    for (int s = 128; s > 0; s >>= 1) {
        if (tid < s) red[tid] += red[tid + s];
        __syncthreads();
    }
    float rstd = rsqrtf(red[0] * (1.f / 1024.f) + 1e-5f);
    float4 g4 = *(const float4*)(g + f);
    float4 be4 = *(const float4*)(beta + f);
    float y[4];
    y[0] = (pre[0] - mu) * rstd * g4.x + be4.x;
    y[1] = (pre[1] - mu) * rstd * g4.y + be4.y;
    y[2] = (pre[2] - mu) * rstd * g4.z + be4.z;
    y[3] = (pre[3] - mu) * rstd * g4.w + be4.w;
#pragma unroll
    for (int k = 0; k < 4; k++) y[k] = (y[k] > 0.f) ? y[k] : expm1f(y[k]);
    uint32_t hw0, lw0, hw1, lw1;
    packpair(y[0], y[1], hw0, lw0);
    packpair(y[2], y[3], hw1, lw1);
    size_t w = (size_t)row * 512 + 2 * tid;
    g_ah[w] = hw0; g_ah[w + 1] = hw1;
    g_al[w] = lw0; g_al[w + 1] = lw1;
}

// ---------------- final head-mean + bias -------------------------------------
__global__ void head_mean_kernel(const float* __restrict__ agg,
                                 const float* __restrict__ b3,
                                 float* __restrict__ out) {
    int idx = blockIdx.x * blockDim.x + threadIdx.x;
    if (idx >= NN * 121) return;
    int n = idx / 121, c = idx % 121;
    float s = 0.f;
#pragma unroll
    for (int h = 0; h < 6; h++) s += agg[(size_t)n * 728 + h * 121 + c];
    out[idx] = s * (1.f / 6.f) + b3[c];
}

// ---------------- host orchestration -----------------------------------------
extern "C" void kernel_launch(void* const* d_in, const int* in_sizes, int n_in,
                              void* d_out, int out_size) {
    const float* x      = (const float*)d_in[0];
    const void*  ei     = d_in[1];
    const float* W1     = (const float*)d_in[2];
    const float* a_src1 = (const float*)d_in[3];
    const float* a_dst1 = (const float*)d_in[4];
    const float* b1     = (const float*)d_in[5];
    const float* W2     = (const float*)d_in[6];
    const float* a_src2 = (const float*)d_in[7];
    const float* a_dst2 = (const float*)d_in[8];
    const float* b2     = (const float*)d_in[9];
    const float* W3     = (const float*)d_in[10];
    const float* a_src3 = (const float*)d_in[11];
    const float* a_dst3 = (const float*)d_in[12];
    const float* b3     = (const float*)d_in[13];
    const float* skipW1 = (const float*)d_in[14];
    const float* skipb1 = (const float*)d_in[15];
    const float* skipW2 = (const float*)d_in[16];
    const float* skipb2 = (const float*)d_in[17];
    const float* g1     = (const float*)d_in[18];
    const float* beta1  = (const float*)d_in[19];
    const float* g2     = (const float*)d_in[20];
    const float* beta2  = (const float*)d_in[21];
    float* out = (float*)d_out;

    float *p_xl, *p_skip, *p_agg;
    uint32_t *p_ah, *p_al, *p_bh, *p_bl;
    cudaGetSymbolAddress((void**)&p_xl, g_xl);
    cudaGetSymbolAddress((void**)&p_skip, g_skip);
    cudaGetSymbolAddress((void**)&p_agg, g_agg);
    cudaGetSymbolAddress((void**)&p_ah, g_ah);
    cudaGetSymbolAddress((void**)&p_al, g_al);
    cudaGetSymbolAddress((void**)&p_bh, g_bh);
    cudaGetSymbolAddress((void**)&p_bl, g_bl);

    cudaFuncSetAttribute(mma_gemm_async,
                         cudaFuncAttributeMaxDynamicSharedMemorySize,
                         GEMM_SMEM_BYTES);

    // ---- CSR build (edges shared by all 3 layers) ----
    detect_dtype_kernel<<<1, 32>>>((const int*)ei);
    zero_deg_kernel<<<(NN + 255) / 256, 256>>>();
    build_edges_kernel<<<(NT + 255) / 256, 256>>>(ei);
    scan_kernel<<<1, 1024>>>();
    scatter_kernel<<<(NT + 255) / 256, 256>>>();

    const int gridM = MPAD / 128;   // 157

    // ---- Layer 1: GATConv(50 -> 256, H=4, concat) + skip; K=50 Kpad=64 ----
    {
        const int K = 50, aStride = 32, nkt = 2, Np = 2048;
        cvt_w_kernel<<<((Np * aStride) + 255) / 256, 256>>>(
            W1, 1024, skipW1, 1024, K, Np, aStride);
        cvt_a_kernel<<<((MPAD * aStride) + 255) / 256, 256>>>(x, NN, K, aStride);
        mma_gemm_async<<<dim3(16, gridM), 256, GEMM_SMEM_BYTES>>>(
            p_ah, p_al, p_bh, p_bl, p_xl, p_skip, NN, aStride, Np,
            1024, 1024, 1024, 1024, nkt);
    }
    compute_alpha_kernel<<<NN, 4 * 32>>>(p_xl, a_src1, a_dst1, 4, 256, 1024);
    edge_softmax_kernel<<<NN, 4 * 32>>>(4);
    gat_gather_kernel<true><<<NN, 256>>>(p_xl, p_agg, 4, 256, 1024, 1024);
    ln_elu_pack_kernel<<<NN, 256>>>(p_agg, b1, p_skip, skipb1, g1, beta1);

    // ---- Layer 2: GATConv(1024 -> 256, H=4, concat) + skip ----
    {
        const int aStride = 512, nkt = 32, Np = 2048;
        cvt_w_kernel<<<((Np * aStride) + 255) / 256, 256>>>(
            W2, 1024, skipW2, 1024, 1024, Np, aStride);
        mma_gemm_async<<<dim3(16, gridM), 256, GEMM_SMEM_BYTES>>>(
            p_ah, p_al, p_bh, p_bl, p_xl, p_skip, NN, aStride, Np,
            1024, 1024, 1024, 1024, nkt);
    }
    compute_alpha_kernel<<<NN, 4 * 32>>>(p_xl, a_src2, a_dst2, 4, 256, 1024);
    edge_softmax_kernel<<<NN, 4 * 32>>>(4);
    gat_gather_kernel<true><<<NN, 256>>>(p_xl, p_agg, 4, 256, 1024, 1024);
    ln_elu_pack_kernel<<<NN, 256>>>(p_agg, b2, p_skip, skipb2, g2, beta2);

    // ---- Layer 3: GATConv(1024 -> 121, H=6, mean); N=726, row stride 728 ----
    {
        const int aStride = 512, nkt = 32, Np = 768;
        cvt_w_kernel<<<((Np * aStride) + 255) / 256, 256>>>(
            W3, 726, (const float*)nullptr, 0, 1024, Np, aStride);
        mma_gemm_async<<<dim3(6, gridM), 256, GEMM_SMEM_BYTES>>>(
            p_ah, p_al, p_bh, p_bl, p_xl, p_xl, NN, aStride, Np,
            726, 728, 0, 728, nkt);
    }
    compute_alpha_kernel<<<NN, 6 * 32>>>(p_xl, a_src3, a_dst3, 6, 121, 728);
    edge_softmax_kernel<<<NN, 6 * 32>>>(6);
    gat_gather_kernel<false><<<NN, 192>>>(p_xl, p_agg, 6, 121, 728, 726);
    head_mean_kernel<<<(NN * 121 + 255) / 256, 256>>>(p_agg, b3, out);
}